// round 5
// baseline (speedup 1.0000x reference)
#include <cuda_runtime.h>
#include <cstddef>

#define Bb 8
#define Hh 16
#define Ll 1024
#define Dd 64
#define BH (Bb*Hh)          // 128
#define DMODEL (Hh*Dd)      // 1024

// scratch (no allocations allowed)
__device__ float g_gate[BH*Ll];            // [bh][k]
__device__ float g_invsum[BH*Ll];          // [bh][q]
__device__ float g_attnout[BH*Ll*Dd];      // [bh][l][d], normalized

// ---------------------------------------------------------------------------
// K1: gate[b,h,k] = sigmoid( tanh(pt @ W1^T + b1) . w2 + b2 )
// one warp per (b,h,k) row
// ---------------------------------------------------------------------------
__global__ __launch_bounds__(256) void gate_kernel(
    const float* __restrict__ pt, const float* __restrict__ W1,
    const float* __restrict__ b1, const float* __restrict__ w2,
    const float* __restrict__ b2)
{
    __shared__ float W1s[64][65];
    __shared__ float w2s[64];
    __shared__ float b1s[64];
    __shared__ float pts[8][64];

    const int tid = threadIdx.x;
    for (int i = tid; i < 64*64; i += 256) W1s[i >> 6][i & 63] = W1[i];
    if (tid < 64) { w2s[tid] = w2[tid]; b1s[tid] = b1[tid]; }
    __syncthreads();

    const int warp = tid >> 5, lane = tid & 31;
    const size_t row = (size_t)blockIdx.x * 8 + warp;   // 0..131071
    const float* p = pt + row * Dd;
    pts[warp][lane]      = p[lane];
    pts[warp][lane + 32] = p[lane + 32];
    __syncwarp();

    float acc0 = 0.f, acc1 = 0.f;
#pragma unroll
    for (int d = 0; d < 64; d++) {
        float x = pts[warp][d];
        acc0 = fmaf(x, W1s[lane][d],      acc0);
        acc1 = fmaf(x, W1s[lane + 32][d], acc1);
    }
    float t0 = tanhf(acc0 + b1s[lane]);
    float t1 = tanhf(acc1 + b1s[lane + 32]);
    float part = t0 * w2s[lane] + t1 * w2s[lane + 32];
#pragma unroll
    for (int off = 16; off > 0; off >>= 1)
        part += __shfl_xor_sync(0xffffffffu, part, off);
    if (lane == 0)
        g_gate[row] = 1.0f / (1.0f + __expf(-(part + b2[0])));
}

// ---------------------------------------------------------------------------
// K2a: for each (bh, 64-q tile):
//   loop over 16 k-tiles of 64:
//     scores = (q*scale) @ k^T + bias ; e = exp(scores)
//     rowsum += e ; w = e*gate[k] ; write w to weights (unnormalized)
//     O += w @ v
//   write invsum, write O/rowsum to g_attnout
// 256 threads, 4x4 register micro-tiles
// ---------------------------------------------------------------------------
__global__ __launch_bounds__(256) void attn_kernel(
    const float* __restrict__ q, const float* __restrict__ k,
    const float* __restrict__ v, const float* __restrict__ bias,
    float* __restrict__ wout)
{
    extern __shared__ float sm[];
    float* qs = sm;                 // 64 x 65
    float* ks = sm + 64*65;         // 64 x 65
    float* vs = sm + 2*64*65;       // 64 x 65
    float* ps = sm + 3*64*65;       // 64 x 65
    float* gs = sm + 4*64*65;       // 64

    const int tid = threadIdx.x;
    const int tx = tid & 15, ty = tid >> 4;
    const int bh = blockIdx.y;
    const int q0 = blockIdx.x * 64;

    const size_t qkv_base = (size_t)bh * Ll * Dd;
    {
        const float* qp = q + qkv_base + (size_t)q0 * Dd;
        for (int i = tid; i < 64*64; i += 256) {
            int r = i >> 6, c = i & 63;
            qs[r*65 + c] = qp[i] * 0.125f;     // 1/sqrt(64)
        }
    }

    float rsum[4] = {0.f, 0.f, 0.f, 0.f};
    float oacc[4][4];
#pragma unroll
    for (int i = 0; i < 4; i++)
#pragma unroll
        for (int j = 0; j < 4; j++) oacc[i][j] = 0.f;

    const size_t bw_base = (size_t)bh * Ll * Ll + (size_t)q0 * Ll;
    const float* biasp = bias + bw_base;
    float* wp = wout + bw_base;

    __syncthreads();

    for (int kt = 0; kt < 16; kt++) {
        {
            const float* kp = k + qkv_base + (size_t)kt * 64 * Dd;
            const float* vp = v + qkv_base + (size_t)kt * 64 * Dd;
            for (int i = tid; i < 64*64; i += 256) {
                int r = i >> 6, c = i & 63;
                ks[r*65 + c] = kp[i];
                vs[r*65 + c] = vp[i];
            }
            if (tid < 64) gs[tid] = g_gate[(size_t)bh * Ll + kt*64 + tid];
        }
        __syncthreads();

        // scores micro-GEMM
        float acc[4][4];
#pragma unroll
        for (int i = 0; i < 4; i++)
#pragma unroll
            for (int j = 0; j < 4; j++) acc[i][j] = 0.f;

#pragma unroll 8
        for (int d = 0; d < 64; d++) {
            float a[4], bb[4];
#pragma unroll
            for (int i = 0; i < 4; i++) a[i]  = qs[(ty*4 + i)*65 + d];
#pragma unroll
            for (int j = 0; j < 4; j++) bb[j] = ks[(tx*4 + j)*65 + d];
#pragma unroll
            for (int i = 0; i < 4; i++)
#pragma unroll
                for (int j = 0; j < 4; j++)
                    acc[i][j] = fmaf(a[i], bb[j], acc[i][j]);
        }

        // epilogue: bias, exp, gate, write weights (unnormalized) + smem P
#pragma unroll
        for (int i = 0; i < 4; i++) {
            const int qr  = ty*4 + i;
            const int kc0 = tx*4;
            float4 bv = *reinterpret_cast<const float4*>(
                biasp + (size_t)qr * Ll + kt*64 + kc0);
            float e0 = __expf(acc[i][0] + bv.x);
            float e1 = __expf(acc[i][1] + bv.y);
            float e2 = __expf(acc[i][2] + bv.z);
            float e3 = __expf(acc[i][3] + bv.w);
            rsum[i] += (e0 + e1) + (e2 + e3);
            float4 wv;
            wv.x = e0 * gs[kc0 + 0];
            wv.y = e1 * gs[kc0 + 1];
            wv.z = e2 * gs[kc0 + 2];
            wv.w = e3 * gs[kc0 + 3];
            ps[qr*65 + kc0 + 0] = wv.x;
            ps[qr*65 + kc0 + 1] = wv.y;
            ps[qr*65 + kc0 + 2] = wv.z;
            ps[qr*65 + kc0 + 3] = wv.w;
            *reinterpret_cast<float4*>(wp + (size_t)qr * Ll + kt*64 + kc0) = wv;
        }
        __syncthreads();

        // O += P @ V  (tx now indexes d-groups)
#pragma unroll 8
        for (int kk = 0; kk < 64; kk++) {
            float a[4], bb[4];
#pragma unroll
            for (int i = 0; i < 4; i++) a[i]  = ps[(ty*4 + i)*65 + kk];
#pragma unroll
            for (int j = 0; j < 4; j++) bb[j] = vs[kk*65 + tx*4 + j];
#pragma unroll
            for (int i = 0; i < 4; i++)
#pragma unroll
                for (int j = 0; j < 4; j++)
                    oacc[i][j] = fmaf(a[i], bb[j], oacc[i][j]);
        }
        __syncthreads();
    }

    // reduce rowsum across the 16 tx lanes sharing each q row
#pragma unroll
    for (int i = 0; i < 4; i++) {
        float r = rsum[i];
        r += __shfl_xor_sync(0xffffffffu, r, 1);
        r += __shfl_xor_sync(0xffffffffu, r, 2);
        r += __shfl_xor_sync(0xffffffffu, r, 4);
        r += __shfl_xor_sync(0xffffffffu, r, 8);
        rsum[i] = r;
    }
    if (tx == 0) {
#pragma unroll
        for (int i = 0; i < 4; i++)
            g_invsum[(size_t)bh * Ll + q0 + ty*4 + i] = 1.0f / rsum[i];
    }
#pragma unroll
    for (int i = 0; i < 4; i++) {
        float inv = 1.0f / rsum[i];
        float4 ov;
        ov.x = oacc[i][0] * inv;
        ov.y = oacc[i][1] * inv;
        ov.z = oacc[i][2] * inv;
        ov.w = oacc[i][3] * inv;
        *reinterpret_cast<float4*>(
            g_attnout + ((size_t)bh * Ll + q0 + ty*4 + i) * Dd + tx*4) = ov;
    }
}

// ---------------------------------------------------------------------------
// K2b: weights row normalize (w *= invsum[row]); one block per row
// ---------------------------------------------------------------------------
__global__ __launch_bounds__(256) void normalize_kernel(float* __restrict__ w)
{
    const size_t row = blockIdx.x;
    const float inv = g_invsum[row];
    float4* p = reinterpret_cast<float4*>(w + row * Ll);
    float4 x = p[threadIdx.x];
    x.x *= inv; x.y *= inv; x.z *= inv; x.w *= inv;
    p[threadIdx.x] = x;
}

// ---------------------------------------------------------------------------
// K3: graph_out[b,l,:] = concat_h attnout[b,h,l,:] @ W_out^T + b_out
// tiled 64x64, K-steps of 32, 4x4 register micro-tiles
// ---------------------------------------------------------------------------
__global__ __launch_bounds__(256) void outproj_kernel(
    const float* __restrict__ W, const float* __restrict__ bo,
    float* __restrict__ out)
{
    __shared__ float As[64][33];
    __shared__ float Ws[64][33];

    const int tid = threadIdx.x;
    const int tx = tid & 15, ty = tid >> 4;
    const int n0   = blockIdx.x * 64;
    const int row0 = blockIdx.y * 64;      // global m = b*1024 + l
    const int b  = row0 >> 10;
    const int l0 = row0 & 1023;

    float acc[4][4];
#pragma unroll
    for (int i = 0; i < 4; i++)
#pragma unroll
        for (int j = 0; j < 4; j++) acc[i][j] = 0.f;

    for (int kt = 0; kt < 32; kt++) {
        const int kg0 = kt * 32;
        const int h   = kg0 >> 6;
        const int dd0 = kg0 & 63;
        const float* ap = g_attnout
            + ((size_t)(b * Hh + h) * Ll + l0) * Dd + dd0;
        for (int i = tid; i < 64*32; i += 256) {
            int r = i >> 5, c = i & 31;
            As[r][c] = ap[(size_t)r * Dd + c];
        }
        const float* wpp = W + (size_t)n0 * DMODEL + kg0;
        for (int i = tid; i < 64*32; i += 256) {
            int r = i >> 5, c = i & 31;
            Ws[r][c] = wpp[(size_t)r * DMODEL + c];
        }
        __syncthreads();

#pragma unroll 8
        for (int c = 0; c < 32; c++) {
            float a[4], bb[4];
#pragma unroll
            for (int i = 0; i < 4; i++) a[i]  = As[ty*4 + i][c];
#pragma unroll
            for (int j = 0; j < 4; j++) bb[j] = Ws[tx*4 + j][c];
#pragma unroll
            for (int i = 0; i < 4; i++)
#pragma unroll
                for (int j = 0; j < 4; j++)
                    acc[i][j] = fmaf(a[i], bb[j], acc[i][j]);
        }
        __syncthreads();
    }

#pragma unroll
    for (int i = 0; i < 4; i++) {
        const int m = row0 + ty*4 + i;
        float4 ov;
        ov.x = acc[i][0] + bo[n0 + tx*4 + 0];
        ov.y = acc[i][1] + bo[n0 + tx*4 + 1];
        ov.z = acc[i][2] + bo[n0 + tx*4 + 2];
        ov.w = acc[i][3] + bo[n0 + tx*4 + 3];
        *reinterpret_cast<float4*>(out + (size_t)m * DMODEL + n0 + tx*4) = ov;
    }
}

// ---------------------------------------------------------------------------
extern "C" void kernel_launch(void* const* d_in, const int* in_sizes, int n_in,
                              void* d_out, int out_size)
{
    const float* q    = (const float*)d_in[0];
    const float* k    = (const float*)d_in[1];
    const float* v    = (const float*)d_in[2];
    const float* pt   = (const float*)d_in[3];
    const float* bias = (const float*)d_in[4];
    const float* W1   = (const float*)d_in[5];
    const float* b1   = (const float*)d_in[6];
    const float* w2   = (const float*)d_in[7];
    const float* b2   = (const float*)d_in[8];
    const float* Wo   = (const float*)d_in[9];
    const float* bo   = (const float*)d_in[10];

    float* graph_out = (float*)d_out;                               // [8,1024,1024]
    float* weights   = (float*)d_out + (size_t)Bb * Ll * DMODEL;    // [8,16,1024,1024]

    const int attn_smem = (4 * 64 * 65 + 64) * (int)sizeof(float);  // 66816 B
    cudaFuncSetAttribute(attn_kernel,
                         cudaFuncAttributeMaxDynamicSharedMemorySize, attn_smem);

    gate_kernel<<<BH * Ll / 8, 256>>>(pt, W1, b1, w2, b2);
    attn_kernel<<<dim3(Ll / 64, BH), 256, attn_smem>>>(q, k, v, bias, weights);
    normalize_kernel<<<BH * Ll, 256>>>(weights);
    outproj_kernel<<<dim3(DMODEL / 64, Bb * Ll / 64), 256>>>(Wo, bo, graph_out);
}

// round 7
// speedup vs baseline: 1.5064x; 1.5064x over previous
#include <cuda_runtime.h>
#include <cuda_bf16.h>
#include <mma.h>
#include <cstdint>
#include <cstddef>

using namespace nvcuda;

#define Bb 8
#define Hh 16
#define Ll 1024
#define Dd 64
#define BH (Bb*Hh)
#define DMODEL (Hh*Dd)
#define LDA 72                      // smem leading dim (elements)

// scratch (no allocations allowed)
__device__ float g_gate[BH*Ll];
__device__ float g_invsum[BH*Ll];
__device__ __nv_bfloat16 g_aoh[(size_t)Bb*Ll*DMODEL];  // attnout hi [b*L+l][h*64+d]
__device__ __nv_bfloat16 g_aol[(size_t)Bb*Ll*DMODEL];  // attnout lo
__device__ __nv_bfloat16 g_woh[DMODEL*DMODEL];         // W_out hi   [n][k]
__device__ __nv_bfloat16 g_wol[DMODEL*DMODEL];         // W_out lo

// ---- split helpers: x = hi(bf16) + lo(bf16) ----
__device__ __forceinline__ void split8(const float* x, uint4& hi, uint4& lo) {
    uint32_t hs[8], ls[8];
#pragma unroll
    for (int j = 0; j < 8; j++) {
        __nv_bfloat16 hb = __float2bfloat16(x[j]);
        __nv_bfloat16 lb = __float2bfloat16(x[j] - __bfloat162float(hb));
        hs[j] = (uint32_t)__bfloat16_as_ushort(hb);
        ls[j] = (uint32_t)__bfloat16_as_ushort(lb);
    }
    hi.x = hs[0]|(hs[1]<<16); hi.y = hs[2]|(hs[3]<<16);
    hi.z = hs[4]|(hs[5]<<16); hi.w = hs[6]|(hs[7]<<16);
    lo.x = ls[0]|(ls[1]<<16); lo.y = ls[2]|(ls[3]<<16);
    lo.z = ls[4]|(ls[5]<<16); lo.w = ls[6]|(ls[7]<<16);
}
__device__ __forceinline__ void split2(float a, float b, uint32_t& h, uint32_t& l) {
    __nv_bfloat16 ha = __float2bfloat16(a), hb = __float2bfloat16(b);
    __nv_bfloat16 la = __float2bfloat16(a - __bfloat162float(ha));
    __nv_bfloat16 lb = __float2bfloat16(b - __bfloat162float(hb));
    h = (uint32_t)__bfloat16_as_ushort(ha) | ((uint32_t)__bfloat16_as_ushort(hb) << 16);
    l = (uint32_t)__bfloat16_as_ushort(la) | ((uint32_t)__bfloat16_as_ushort(lb) << 16);
}

typedef wmma::fragment<wmma::matrix_a, 16, 16, 16, __nv_bfloat16, wmma::row_major> FragA;
typedef wmma::fragment<wmma::matrix_b, 16, 16, 16, __nv_bfloat16, wmma::col_major> FragBc;
typedef wmma::fragment<wmma::matrix_b, 16, 16, 16, __nv_bfloat16, wmma::row_major> FragBr;
typedef wmma::fragment<wmma::accumulator, 16, 16, 16, float> FragC;

// ---------------- K1: gate ----------------
__global__ __launch_bounds__(256) void gate_kernel(
    const float* __restrict__ pt, const float* __restrict__ W1,
    const float* __restrict__ b1, const float* __restrict__ w2,
    const float* __restrict__ b2)
{
    __shared__ float W1s[64][65];
    __shared__ float w2s[64], b1s[64], pts[8][64];
    const int tid = threadIdx.x;
    for (int i = tid; i < 64*64; i += 256) W1s[i >> 6][i & 63] = W1[i];
    if (tid < 64) { w2s[tid] = w2[tid]; b1s[tid] = b1[tid]; }
    __syncthreads();
    const int warp = tid >> 5, lane = tid & 31;
    const size_t row = (size_t)blockIdx.x * 8 + warp;
    const float* p = pt + row * Dd;
    pts[warp][lane] = p[lane];
    pts[warp][lane + 32] = p[lane + 32];
    __syncwarp();
    float a0 = 0.f, a1 = 0.f;
#pragma unroll
    for (int d = 0; d < 64; d++) {
        float x = pts[warp][d];
        a0 = fmaf(x, W1s[lane][d], a0);
        a1 = fmaf(x, W1s[lane + 32][d], a1);
    }
    float part = tanhf(a0 + b1s[lane]) * w2s[lane]
               + tanhf(a1 + b1s[lane + 32]) * w2s[lane + 32];
#pragma unroll
    for (int off = 16; off > 0; off >>= 1)
        part += __shfl_xor_sync(0xffffffffu, part, off);
    if (lane == 0)
        g_gate[row] = 1.0f / (1.0f + __expf(-(part + b2[0])));
}

// ---------------- prep: W_out -> bf16 hi/lo ----------------
__global__ __launch_bounds__(256) void prep_wo_kernel(const float* __restrict__ W)
{
    int i = blockIdx.x * 256 + threadIdx.x;
    float x = W[i];
    __nv_bfloat16 h = __float2bfloat16(x);
    g_woh[i] = h;
    g_wol[i] = __float2bfloat16(x - __bfloat162float(h));
}

// ---------------- attn: wmma bf16 split, CTA = (bh, 128 q rows) ----------------
// smem byte offsets
#define A_QH 0u          // 128 x 72 bf16 = 18432
#define A_QL 18432u
#define A_KH 36864u      // 64 x 72 bf16 = 9216
#define A_KL 46080u
#define A_VH 55296u
#define A_VL 64512u
#define A_SC 73728u      // 128 x 72 f32 = 36864 (scores / O staging)
#define A_PH 73728u      // P hi aliases SC (guarded by syncs)
#define A_PL 92160u
#define A_GT 110592u     // 64 floats
#define ATTN_SMEM 110848

__global__ __launch_bounds__(256, 2) void attn_wmma(
    const float* __restrict__ q, const float* __restrict__ k,
    const float* __restrict__ v, const float* __restrict__ bias,
    float* __restrict__ wout)
{
    extern __shared__ char sm[];
    __nv_bfloat16* qh  = (__nv_bfloat16*)(sm + A_QH);
    __nv_bfloat16* ql  = (__nv_bfloat16*)(sm + A_QL);
    __nv_bfloat16* ksh = (__nv_bfloat16*)(sm + A_KH);
    __nv_bfloat16* ksl = (__nv_bfloat16*)(sm + A_KL);
    __nv_bfloat16* vsh = (__nv_bfloat16*)(sm + A_VH);
    __nv_bfloat16* vsl = (__nv_bfloat16*)(sm + A_VL);
    float*         scf = (float*)(sm + A_SC);
    __nv_bfloat16* psh = (__nv_bfloat16*)(sm + A_PH);
    __nv_bfloat16* psl = (__nv_bfloat16*)(sm + A_PL);
    float*         gt  = (float*)(sm + A_GT);

    const int tid = threadIdx.x;
    const int w   = tid >> 5;
    const int bh  = blockIdx.y, b = bh >> 4, h = bh & 15;
    const int q0  = blockIdx.x * 128;
    const size_t kvb = (size_t)bh * Ll * Dd;

    // Q tile: load, scale, split
    {
        const float* qp = q + kvb + (size_t)q0 * Dd;
#pragma unroll
        for (int i = tid; i < 1024; i += 256) {
            int r = i >> 3, c8 = (i & 7) * 8;
            const float* s0 = qp + r * 64 + c8;
            float4 a = *(const float4*)s0, bq = *(const float4*)(s0 + 4);
            float x[8] = {a.x*.125f, a.y*.125f, a.z*.125f, a.w*.125f,
                          bq.x*.125f, bq.y*.125f, bq.z*.125f, bq.w*.125f};
            uint4 hi, lo; split8(x, hi, lo);
            *(uint4*)(sm + A_QH + r*144 + c8*2) = hi;
            *(uint4*)(sm + A_QL + r*144 + c8*2) = lo;
        }
    }

    FragC acc_o[4];
#pragma unroll
    for (int d = 0; d < 4; d++) wmma::fill_fragment(acc_o[d], 0.0f);

    float rsum = 0.0f;
    const int er = tid >> 1;            // epilogue row 0..127
    const int hc = (tid & 1) * 32;      // epilogue col half
    const size_t browb = (size_t)bh * Ll * Ll + (size_t)(q0 + er) * Ll + hc;

    for (int kt = 0; kt < 16; kt++) {
        // K & V tiles: load + split (row-major, no transpose needed)
        {
            const float* kp = k + kvb + (size_t)kt * 64 * Dd;
            const float* vp = v + kvb + (size_t)kt * 64 * Dd;
#pragma unroll
            for (int i = tid; i < 512; i += 256) {
                int r = i >> 3, c8 = (i & 7) * 8;
                const float* s0 = kp + r * 64 + c8;
                float4 a = *(const float4*)s0, bq = *(const float4*)(s0 + 4);
                float x[8] = {a.x, a.y, a.z, a.w, bq.x, bq.y, bq.z, bq.w};
                uint4 hi, lo; split8(x, hi, lo);
                *(uint4*)(sm + A_KH + r*144 + c8*2) = hi;
                *(uint4*)(sm + A_KL + r*144 + c8*2) = lo;
                const float* t0 = vp + r * 64 + c8;
                float4 va = *(const float4*)t0, vb = *(const float4*)(t0 + 4);
                float y[8] = {va.x, va.y, va.z, va.w, vb.x, vb.y, vb.z, vb.w};
                split8(y, hi, lo);
                *(uint4*)(sm + A_VH + r*144 + c8*2) = hi;
                *(uint4*)(sm + A_VL + r*144 + c8*2) = lo;
            }
            if (tid < 64) gt[tid] = g_gate[(size_t)bh * Ll + kt * 64 + tid];
        }
        __syncthreads();

        // scores = (Qh+Ql)(Kh+Kl)^T  (3 terms)
        {
            FragA ah[4], al[4];
#pragma unroll
            for (int kc = 0; kc < 4; kc++) {
                wmma::load_matrix_sync(ah[kc], qh + w*16*LDA + kc*16, LDA);
                wmma::load_matrix_sync(al[kc], ql + w*16*LDA + kc*16, LDA);
            }
#pragma unroll
            for (int n = 0; n < 4; n++) {
                FragC acc;
                wmma::fill_fragment(acc, 0.0f);
#pragma unroll
                for (int kc = 0; kc < 4; kc++) {
                    FragBc bhf, blf;
                    wmma::load_matrix_sync(bhf, ksh + n*16*LDA + kc*16, LDA);
                    wmma::load_matrix_sync(blf, ksl + n*16*LDA + kc*16, LDA);
                    wmma::mma_sync(acc, ah[kc], bhf, acc);
                    wmma::mma_sync(acc, al[kc], bhf, acc);
                    wmma::mma_sync(acc, ah[kc], blf, acc);
                }
                wmma::store_matrix_sync(scf + w*16*LDA + n*16, acc, LDA,
                                        wmma::mem_row_major);
            }
        }
        __syncthreads();

        // epilogue pass1: +bias, exp, rsum, *gate, STG weights, keep in regs
        float su[32];
        {
            const float* brow = bias + browb + kt * 64;
            float* wrow = wout + browb + kt * 64;
#pragma unroll
            for (int c4 = 0; c4 < 8; c4++) {
                float4 sv = *(float4*)(scf + er*LDA + hc + c4*4);
                float4 bv = *(const float4*)(brow + c4*4);
                float e0 = __expf(sv.x + bv.x);
                float e1 = __expf(sv.y + bv.y);
                float e2 = __expf(sv.z + bv.z);
                float e3 = __expf(sv.w + bv.w);
                rsum += (e0 + e1) + (e2 + e3);
                float4 wv;
                wv.x = e0 * gt[hc + c4*4 + 0];
                wv.y = e1 * gt[hc + c4*4 + 1];
                wv.z = e2 * gt[hc + c4*4 + 2];
                wv.w = e3 * gt[hc + c4*4 + 3];
                su[c4*4+0] = wv.x; su[c4*4+1] = wv.y;
                su[c4*4+2] = wv.z; su[c4*4+3] = wv.w;
                *(float4*)(wrow + c4*4) = wv;
            }
        }
        __syncthreads();

        // pass2: P split hi/lo into smem (aliases score region; sync-guarded)
        {
#pragma unroll
            for (int v4 = 0; v4 < 4; v4++) {
                uint4 hi, lo; split8(su + v4*8, hi, lo);
                *(uint4*)(sm + A_PH + er*144 + (hc + v4*8)*2) = hi;
                *(uint4*)(sm + A_PL + er*144 + (hc + v4*8)*2) = lo;
            }
        }
        __syncthreads();

        // O += (Ph+Pl)(Vh+Vl)  (3 terms)
        {
            FragA pah[4], pal[4];
#pragma unroll
            for (int kc = 0; kc < 4; kc++) {
                wmma::load_matrix_sync(pah[kc], psh + w*16*LDA + kc*16, LDA);
                wmma::load_matrix_sync(pal[kc], psl + w*16*LDA + kc*16, LDA);
            }
#pragma unroll
            for (int d = 0; d < 4; d++) {
#pragma unroll
                for (int kc = 0; kc < 4; kc++) {
                    FragBr vbh, vbl;
                    wmma::load_matrix_sync(vbh, vsh + kc*16*LDA + d*16, LDA);
                    wmma::load_matrix_sync(vbl, vsl + kc*16*LDA + d*16, LDA);
                    wmma::mma_sync(acc_o[d], pah[kc], vbh, acc_o[d]);
                    wmma::mma_sync(acc_o[d], pal[kc], vbh, acc_o[d]);
                    wmma::mma_sync(acc_o[d], pah[kc], vbl, acc_o[d]);
                }
            }
        }
        __syncthreads();
    }

    // stage O, normalize, split to g_ao hi/lo
#pragma unroll
    for (int d = 0; d < 4; d++)
        wmma::store_matrix_sync(scf + w*16*LDA + d*16, acc_o[d], LDA,
                                wmma::mem_row_major);
    __syncthreads();
    {
        float full = rsum + __shfl_xor_sync(0xffffffffu, rsum, 1);
        float inv = 1.0f / full;
        if ((tid & 1) == 0) g_invsum[(size_t)bh * Ll + q0 + er] = inv;
        size_t mrow = (size_t)b * 1024 + q0 + er;
        uint32_t* dh = (uint32_t*)g_aoh + mrow * (DMODEL/2) + h * 32 + (tid & 1) * 16;
        uint32_t* dl = (uint32_t*)g_aol + mrow * (DMODEL/2) + h * 32 + (tid & 1) * 16;
#pragma unroll
        for (int i = 0; i < 16; i++) {
            uint32_t hh, ll;
            split2(scf[er*LDA + hc + 2*i]     * inv,
                   scf[er*LDA + hc + 2*i + 1] * inv, hh, ll);
            dh[i] = hh; dl[i] = ll;
        }
    }
}

// ---------------- normalize ----------------
__global__ __launch_bounds__(256) void normalize_kernel(float* __restrict__ w)
{
    const size_t row = blockIdx.x;
    const float inv = g_invsum[row];
    float4* p = reinterpret_cast<float4*>(w + row * Ll);
    float4 x = p[threadIdx.x];
    x.x *= inv; x.y *= inv; x.z *= inv; x.w *= inv;
    p[threadIdx.x] = x;
}

// ---------------- outproj: wmma, 128x128 tiles, K=1024 ----------------
#define O_AH 0u          // 128 x 72 bf16 = 18432
#define O_AL 18432u
#define O_BH 36864u
#define O_BL 55296u
#define O_BR 73728u      // bias broadcast 16 x 128 f32 = 8192
#define OUT_SMEM 81920

__global__ __launch_bounds__(256, 2) void outproj_wmma(
    const float* __restrict__ bo, float* __restrict__ out)
{
    extern __shared__ char sm[];
    __nv_bfloat16* ash = (__nv_bfloat16*)(sm + O_AH);
    __nv_bfloat16* asl = (__nv_bfloat16*)(sm + O_AL);
    __nv_bfloat16* bsh = (__nv_bfloat16*)(sm + O_BH);
    __nv_bfloat16* bsl = (__nv_bfloat16*)(sm + O_BL);
    float*         br  = (float*)(sm + O_BR);

    const int tid = threadIdx.x;
    const int w = tid >> 5, mw = w >> 2, nw = w & 3;
    const int n0 = blockIdx.x * 128;
    const int m0 = blockIdx.y * 128;

    for (int i = tid; i < 2048; i += 256) br[i] = bo[n0 + (i & 127)];
    __syncthreads();

    FragC acc[4][2];
#pragma unroll
    for (int mi = 0; mi < 4; mi++)
#pragma unroll
        for (int ni = 0; ni < 2; ni++)
            wmma::load_matrix_sync(acc[mi][ni], br + nw*32 + ni*16, 128,
                                   wmma::mem_row_major);

    const uint32_t* aoh = (const uint32_t*)g_aoh;
    const uint32_t* aol = (const uint32_t*)g_aol;
    const uint32_t* woh = (const uint32_t*)g_woh;
    const uint32_t* wol = (const uint32_t*)g_wol;

    for (int kt = 0; kt < 16; kt++) {
        __syncthreads();
#pragma unroll 4
        for (int i = tid; i < 4096; i += 256) {
            int row = i >> 5, c = i & 31;
            uint32_t off = row * 36 + c;                 // LDA=72 bf16 = 36 u32
            size_t ai = (size_t)(m0 + row) * 512 + kt * 32 + c;
            size_t bi = (size_t)(n0 + row) * 512 + kt * 32 + c;
            ((uint32_t*)ash)[off] = aoh[ai];
            ((uint32_t*)asl)[off] = aol[ai];
            ((uint32_t*)bsh)[off] = woh[bi];
            ((uint32_t*)bsl)[off] = wol[bi];
        }
        __syncthreads();

#pragma unroll
        for (int kc = 0; kc < 4; kc++) {
#pragma unroll
            for (int mi = 0; mi < 4; mi++) {
                FragA ah, al;
                wmma::load_matrix_sync(ah, ash + (mw*64 + mi*16)*LDA + kc*16, LDA);
                wmma::load_matrix_sync(al, asl + (mw*64 + mi*16)*LDA + kc*16, LDA);
#pragma unroll
                for (int ni = 0; ni < 2; ni++) {
                    FragBc bhf, blf;
                    wmma::load_matrix_sync(bhf, bsh + (nw*32 + ni*16)*LDA + kc*16, LDA);
                    wmma::load_matrix_sync(blf, bsl + (nw*32 + ni*16)*LDA + kc*16, LDA);
                    wmma::mma_sync(acc[mi][ni], ah, bhf, acc[mi][ni]);
                    wmma::mma_sync(acc[mi][ni], al, bhf, acc[mi][ni]);
                    wmma::mma_sync(acc[mi][ni], ah, blf, acc[mi][ni]);
                }
            }
        }
    }

#pragma unroll
    for (int mi = 0; mi < 4; mi++)
#pragma unroll
        for (int ni = 0; ni < 2; ni++)
            wmma::store_matrix_sync(
                out + (size_t)(m0 + mw*64 + mi*16) * DMODEL + n0 + nw*32 + ni*16,
                acc[mi][ni], DMODEL, wmma::mem_row_major);
}

// ---------------------------------------------------------------------------
extern "C" void kernel_launch(void* const* d_in, const int* in_sizes, int n_in,
                              void* d_out, int out_size)
{
    const float* q    = (const float*)d_in[0];
    const float* k    = (const float*)d_in[1];
    const float* v    = (const float*)d_in[2];
    const float* pt   = (const float*)d_in[3];
    const float* bias = (const float*)d_in[4];
    const float* W1   = (const float*)d_in[5];
    const float* b1   = (const float*)d_in[6];
    const float* w2   = (const float*)d_in[7];
    const float* b2   = (const float*)d_in[8];
    const float* Wo   = (const float*)d_in[9];
    const float* bo   = (const float*)d_in[10];

    float* graph_out = (float*)d_out;                              // [8,1024,1024]
    float* weights   = (float*)d_out + (size_t)Bb * Ll * DMODEL;   // [8,16,1024,1024]

    cudaFuncSetAttribute(attn_wmma,
        cudaFuncAttributeMaxDynamicSharedMemorySize, ATTN_SMEM);
    cudaFuncSetAttribute(outproj_wmma,
        cudaFuncAttributeMaxDynamicSharedMemorySize, OUT_SMEM);

    gate_kernel<<<BH * Ll / 8, 256>>>(pt, W1, b1, w2, b2);
    prep_wo_kernel<<<DMODEL * DMODEL / 256, 256>>>(Wo);
    attn_wmma<<<dim3(Ll / 128, BH), 256, ATTN_SMEM>>>(q, k, v, bias, weights);
    normalize_kernel<<<BH * Ll, 256>>>(weights);
    outproj_wmma<<<dim3(DMODEL / 128, Bb * Ll / 128), 256, OUT_SMEM>>>(bo, graph_out);
}

// round 9
// speedup vs baseline: 2.1328x; 1.4158x over previous
#include <cuda_runtime.h>
#include <cuda_bf16.h>
#include <mma.h>
#include <cstdint>
#include <cstddef>

using namespace nvcuda;

#define Bb 8
#define Hh 16
#define Ll 1024
#define Dd 64
#define BH (Bb*Hh)
#define DMODEL (Hh*Dd)
#define LDA 72                      // smem leading dim (bf16 elements); row stride 144 B

// scratch (no allocations allowed)
__device__ float g_gate[BH*Ll];
__device__ float g_invsum[BH*Ll];
__device__ __nv_bfloat16 g_aoh[(size_t)Bb*Ll*DMODEL];  // attnout hi [b*L+l][h*64+d]
__device__ __nv_bfloat16 g_aol[(size_t)Bb*Ll*DMODEL];  // attnout lo
__device__ __nv_bfloat16 g_woh[DMODEL*DMODEL];         // W_out hi   [n][k]
__device__ __nv_bfloat16 g_wol[DMODEL*DMODEL];         // W_out lo

// ---- split helpers: x = hi(bf16) + lo(bf16) ----
__device__ __forceinline__ void split8(const float* x, uint4& hi, uint4& lo) {
    uint32_t hs[8], ls[8];
#pragma unroll
    for (int j = 0; j < 8; j++) {
        __nv_bfloat16 hb = __float2bfloat16(x[j]);
        __nv_bfloat16 lb = __float2bfloat16(x[j] - __bfloat162float(hb));
        hs[j] = (uint32_t)__bfloat16_as_ushort(hb);
        ls[j] = (uint32_t)__bfloat16_as_ushort(lb);
    }
    hi.x = hs[0]|(hs[1]<<16); hi.y = hs[2]|(hs[3]<<16);
    hi.z = hs[4]|(hs[5]<<16); hi.w = hs[6]|(hs[7]<<16);
    lo.x = ls[0]|(ls[1]<<16); lo.y = ls[2]|(ls[3]<<16);
    lo.z = ls[4]|(ls[5]<<16); lo.w = ls[6]|(ls[7]<<16);
}
__device__ __forceinline__ void split2(float a, float b, uint32_t& h, uint32_t& l) {
    __nv_bfloat16 ha = __float2bfloat16(a), hb = __float2bfloat16(b);
    __nv_bfloat16 la = __float2bfloat16(a - __bfloat162float(ha));
    __nv_bfloat16 lb = __float2bfloat16(b - __bfloat162float(hb));
    h = (uint32_t)__bfloat16_as_ushort(ha) | ((uint32_t)__bfloat16_as_ushort(hb) << 16);
    l = (uint32_t)__bfloat16_as_ushort(la) | ((uint32_t)__bfloat16_as_ushort(lb) << 16);
}

// ---- raw tensor-core primitives (baseline PTX, assembles for compute_103) ----
__device__ __forceinline__ void ldsm4(uint32_t* r, uint32_t a) {
    asm volatile("ldmatrix.sync.aligned.m8n8.x4.shared.b16 {%0,%1,%2,%3}, [%4];"
        : "=r"(r[0]), "=r"(r[1]), "=r"(r[2]), "=r"(r[3]) : "r"(a));
}
__device__ __forceinline__ void ldsm2(uint32_t* r, uint32_t a) {
    asm volatile("ldmatrix.sync.aligned.m8n8.x2.shared.b16 {%0,%1}, [%2];"
        : "=r"(r[0]), "=r"(r[1]) : "r"(a));
}
__device__ __forceinline__ void ldsm2t(uint32_t* r, uint32_t a) {
    asm volatile("ldmatrix.sync.aligned.m8n8.x2.trans.shared.b16 {%0,%1}, [%2];"
        : "=r"(r[0]), "=r"(r[1]) : "r"(a));
}
__device__ __forceinline__ void mma16816(float* c, const uint32_t* a, const uint32_t* b) {
    asm volatile("mma.sync.aligned.m16n8k16.row.col.f32.bf16.bf16.f32 "
        "{%0,%1,%2,%3}, {%4,%5,%6,%7}, {%8,%9}, {%0,%1,%2,%3};"
        : "+f"(c[0]), "+f"(c[1]), "+f"(c[2]), "+f"(c[3])
        : "r"(a[0]), "r"(a[1]), "r"(a[2]), "r"(a[3]), "r"(b[0]), "r"(b[1]));
}
__device__ __forceinline__ uint32_t smem_u32(const void* p) {
    uint32_t a;
    asm("{ .reg .u64 t; cvta.to.shared.u64 t, %1; cvt.u32.u64 %0, t; }"
        : "=r"(a) : "l"(p));
    return a;
}

typedef wmma::fragment<wmma::matrix_a, 16, 16, 16, __nv_bfloat16, wmma::row_major> FragA;
typedef wmma::fragment<wmma::matrix_b, 16, 16, 16, __nv_bfloat16, wmma::col_major> FragBc;
typedef wmma::fragment<wmma::accumulator, 16, 16, 16, float> FragC;

// ---------------- K1: gate ----------------
__global__ __launch_bounds__(256) void gate_kernel(
    const float* __restrict__ pt, const float* __restrict__ W1,
    const float* __restrict__ b1, const float* __restrict__ w2,
    const float* __restrict__ b2)
{
    __shared__ float W1s[64][65];
    __shared__ float w2s[64], b1s[64], pts[8][64];
    const int tid = threadIdx.x;
    for (int i = tid; i < 64*64; i += 256) W1s[i >> 6][i & 63] = W1[i];
    if (tid < 64) { w2s[tid] = w2[tid]; b1s[tid] = b1[tid]; }
    __syncthreads();
    const int warp = tid >> 5, lane = tid & 31;
    const size_t row = (size_t)blockIdx.x * 8 + warp;
    const float* p = pt + row * Dd;
    pts[warp][lane] = p[lane];
    pts[warp][lane + 32] = p[lane + 32];
    __syncwarp();
    float a0 = 0.f, a1 = 0.f;
#pragma unroll
    for (int d = 0; d < 64; d++) {
        float x = pts[warp][d];
        a0 = fmaf(x, W1s[lane][d], a0);
        a1 = fmaf(x, W1s[lane + 32][d], a1);
    }
    float part = tanhf(a0 + b1s[lane]) * w2s[lane]
               + tanhf(a1 + b1s[lane + 32]) * w2s[lane + 32];
#pragma unroll
    for (int off = 16; off > 0; off >>= 1)
        part += __shfl_xor_sync(0xffffffffu, part, off);
    if (lane == 0)
        g_gate[row] = 1.0f / (1.0f + __expf(-(part + b2[0])));
}

// ---------------- prep: W_out -> bf16 hi/lo ----------------
__global__ __launch_bounds__(256) void prep_wo_kernel(const float* __restrict__ W)
{
    int i = blockIdx.x * 256 + threadIdx.x;
    float x = W[i];
    __nv_bfloat16 h = __float2bfloat16(x);
    g_woh[i] = h;
    g_wol[i] = __float2bfloat16(x - __bfloat162float(h));
}

// ---------------- attn: raw mma, register-resident FMHA style ----------------
// smem byte offsets
#define S_QH 0u          // 128 x 72 bf16 = 18432
#define S_QL 18432u
#define S_KH 36864u      // 64 x 72 bf16 = 9216
#define S_KL 46080u
#define S_VH 55296u
#define S_VL 64512u
#define S_GT 73728u      // 64 floats
#define ATTN2_SMEM 73984

__global__ __launch_bounds__(256, 2) void attn_mma(
    const float* __restrict__ q, const float* __restrict__ k,
    const float* __restrict__ v, const float* __restrict__ bias,
    float* __restrict__ wout)
{
    extern __shared__ char sm[];
    const uint32_t sb = smem_u32(sm);
    float* gt = (float*)(sm + S_GT);

    const int tid = threadIdx.x, wp = tid >> 5, lane = tid & 31;
    const int g = lane >> 2, t = lane & 3;
    const int bh = blockIdx.y, b = bh >> 4, h = bh & 15;
    const int q0 = blockIdx.x * 128;
    const size_t kvb = (size_t)bh * Ll * Dd;
    const int r0 = wp * 16;

    // ---- Q tile: load, scale, split (once) ----
    {
        const float* qp = q + kvb + (size_t)q0 * Dd;
#pragma unroll
        for (int i = tid; i < 1024; i += 256) {
            int r = i >> 3, c8 = (i & 7) * 8;
            const float* s0 = qp + r * 64 + c8;
            float4 a = *(const float4*)s0, bq = *(const float4*)(s0 + 4);
            float x[8] = {a.x*.125f, a.y*.125f, a.z*.125f, a.w*.125f,
                          bq.x*.125f, bq.y*.125f, bq.z*.125f, bq.w*.125f};
            uint4 hi, lo; split8(x, hi, lo);
            *(uint4*)(sm + S_QH + r*144 + c8*2) = hi;
            *(uint4*)(sm + S_QL + r*144 + c8*2) = lo;
        }
    }

    // ldmatrix lane-address bases
    const int a_row = r0 + (lane & 7) + ((lane >> 3) & 1) * 8;  // A (Q) x4
    const int a_col = (lane >> 4) * 8;
    const uint32_t qhA = sb + S_QH + a_row*144 + a_col*2;
    const uint32_t qlA = sb + S_QL + a_row*144 + a_col*2;
    const int b_row = lane & 7;                                  // B (K) x2
    const int b_col = ((lane >> 3) & 1) * 8;
    const uint32_t khB = sb + S_KH + b_row*144 + b_col*2;
    const uint32_t klB = sb + S_KL + b_row*144 + b_col*2;
    const int v_row = (lane & 7) + ((lane >> 3) & 1) * 8;        // B (V) x2 trans
    const uint32_t vhB = sb + S_VH + v_row*144;
    const uint32_t vlB = sb + S_VL + v_row*144;

    float oacc[8][4];
#pragma unroll
    for (int c = 0; c < 8; c++)
#pragma unroll
        for (int j = 0; j < 4; j++) oacc[c][j] = 0.f;
    float rs0 = 0.f, rs1 = 0.f;

    const size_t rowg  = (size_t)bh * Ll * Ll + (size_t)(q0 + r0 + g) * Ll;
    const size_t rowg8 = rowg + 8 * (size_t)Ll;

    for (int kt = 0; kt < 16; kt++) {
        // ---- K/V tile: load + split ----
        {
            const float* kp = k + kvb + (size_t)kt * 64 * Dd;
            const float* vp = v + kvb + (size_t)kt * 64 * Dd;
#pragma unroll
            for (int i = tid; i < 512; i += 256) {
                int r = i >> 3, c8 = (i & 7) * 8;
                const float* s0 = kp + r * 64 + c8;
                float4 a = *(const float4*)s0, bq = *(const float4*)(s0 + 4);
                float x[8] = {a.x, a.y, a.z, a.w, bq.x, bq.y, bq.z, bq.w};
                uint4 hi, lo; split8(x, hi, lo);
                *(uint4*)(sm + S_KH + r*144 + c8*2) = hi;
                *(uint4*)(sm + S_KL + r*144 + c8*2) = lo;
                const float* t0 = vp + r * 64 + c8;
                float4 va = *(const float4*)t0, vb = *(const float4*)(t0 + 4);
                float y[8] = {va.x, va.y, va.z, va.w, vb.x, vb.y, vb.z, vb.w};
                split8(y, hi, lo);
                *(uint4*)(sm + S_VH + r*144 + c8*2) = hi;
                *(uint4*)(sm + S_VL + r*144 + c8*2) = lo;
            }
            if (tid < 64)
                gt[tid] = __ldg(&g_gate[(size_t)bh * Ll + kt * 64 + tid]);
        }
        __syncthreads();

        // ---- QK^T: sacc[c] = (Qh+Ql)K^T 3-term, all in regs ----
        float sacc[8][4];
#pragma unroll
        for (int c = 0; c < 8; c++)
#pragma unroll
            for (int j = 0; j < 4; j++) sacc[c][j] = 0.f;

#pragma unroll
        for (int kc = 0; kc < 4; kc++) {
            uint32_t ah[4], al[4];
            ldsm4(ah, qhA + kc*32);
            ldsm4(al, qlA + kc*32);
#pragma unroll
            for (int c = 0; c < 8; c++) {
                uint32_t bh2[2], bl2[2];
                ldsm2(bh2, khB + c*1152 + kc*32);
                ldsm2(bl2, klB + c*1152 + kc*32);
                mma16816(sacc[c], ah, bh2);
                mma16816(sacc[c], al, bh2);
                mma16816(sacc[c], ah, bl2);
            }
        }

        // ---- in-register epilogue: +bias, exp, rsum, *gate, STG weights ----
        {
            const float* bg  = bias + rowg  + kt*64 + 2*t;
            const float* bg8 = bias + rowg8 + kt*64 + 2*t;
            float* wg  = wout + rowg  + kt*64 + 2*t;
            float* wg8 = wout + rowg8 + kt*64 + 2*t;
#pragma unroll
            for (int c = 0; c < 8; c++) {
                float2 bv0 = *(const float2*)(bg  + c*8);
                float2 bv1 = *(const float2*)(bg8 + c*8);
                float e00 = __expf(sacc[c][0] + bv0.x);
                float e01 = __expf(sacc[c][1] + bv0.y);
                float e10 = __expf(sacc[c][2] + bv1.x);
                float e11 = __expf(sacc[c][3] + bv1.y);
                rs0 += e00 + e01;
                rs1 += e10 + e11;
                float2 gv = *(float2*)(gt + c*8 + 2*t);
                float w00 = e00 * gv.x, w01 = e01 * gv.y;
                float w10 = e10 * gv.x, w11 = e11 * gv.y;
                float2 o0 = {w00, w01}, o1 = {w10, w11};
                *(float2*)(wg  + c*8) = o0;
                *(float2*)(wg8 + c*8) = o1;
                sacc[c][0] = w00; sacc[c][1] = w01;
                sacc[c][2] = w10; sacc[c][3] = w11;
            }
        }

        // ---- P·V: O += (Ph+Pl)(Vh+Vl) 3-term; P fragments built in-register ----
#pragma unroll
        for (int kc = 0; kc < 4; kc++) {
            uint32_t ph[4], pl[4];
            split2(sacc[2*kc][0],   sacc[2*kc][1],   ph[0], pl[0]);
            split2(sacc[2*kc][2],   sacc[2*kc][3],   ph[1], pl[1]);
            split2(sacc[2*kc+1][0], sacc[2*kc+1][1], ph[2], pl[2]);
            split2(sacc[2*kc+1][2], sacc[2*kc+1][3], ph[3], pl[3]);
#pragma unroll
            for (int cd = 0; cd < 8; cd++) {
                uint32_t vh2[2], vl2[2];
                ldsm2t(vh2, vhB + kc*2304 + cd*16);
                ldsm2t(vl2, vlB + kc*2304 + cd*16);
                mma16816(oacc[cd], ph, vh2);
                mma16816(oacc[cd], pl, vh2);
                mma16816(oacc[cd], ph, vl2);
            }
        }
        __syncthreads();
    }

    // ---- rowsum reduce (within quad), invsum, normalized O -> g_ao hi/lo ----
    rs0 += __shfl_xor_sync(0xffffffffu, rs0, 1);
    rs0 += __shfl_xor_sync(0xffffffffu, rs0, 2);
    rs1 += __shfl_xor_sync(0xffffffffu, rs1, 1);
    rs1 += __shfl_xor_sync(0xffffffffu, rs1, 2);
    const float inv0 = 1.0f / rs0, inv1 = 1.0f / rs1;
    if (t == 0) {
        g_invsum[(size_t)bh * Ll + q0 + r0 + g]     = inv0;
        g_invsum[(size_t)bh * Ll + q0 + r0 + g + 8] = inv1;
    }
    {
        const size_t m0r = (size_t)b * 1024 + q0 + r0 + g;
        uint32_t* dh0 = (uint32_t*)g_aoh + m0r * (DMODEL/2) + h * 32;
        uint32_t* dl0 = (uint32_t*)g_aol + m0r * (DMODEL/2) + h * 32;
        uint32_t* dh8 = dh0 + 8 * (DMODEL/2);
        uint32_t* dl8 = dl0 + 8 * (DMODEL/2);
#pragma unroll
        for (int cd = 0; cd < 8; cd++) {
            uint32_t hh, ll;
            split2(oacc[cd][0] * inv0, oacc[cd][1] * inv0, hh, ll);
            dh0[cd*4 + t] = hh; dl0[cd*4 + t] = ll;
            split2(oacc[cd][2] * inv1, oacc[cd][3] * inv1, hh, ll);
            dh8[cd*4 + t] = hh; dl8[cd*4 + t] = ll;
        }
    }
}

// ---------------- normalize ----------------
__global__ __launch_bounds__(256) void normalize_kernel(float* __restrict__ w)
{
    const size_t row = blockIdx.x;
    const float inv = g_invsum[row];
    float4* p = reinterpret_cast<float4*>(w + row * Ll);
    float4 x = p[threadIdx.x];
    x.x *= inv; x.y *= inv; x.z *= inv; x.w *= inv;
    p[threadIdx.x] = x;
}

// ---------------- outproj: wmma, 128x128 tiles, K=1024 (unchanged from R7) ----
#define O_AH 0u
#define O_AL 18432u
#define O_BH 36864u
#define O_BL 55296u
#define O_BR 73728u
#define OUT_SMEM 81920

__global__ __launch_bounds__(256, 2) void outproj_wmma(
    const float* __restrict__ bo, float* __restrict__ out)
{
    extern __shared__ char sm[];
    __nv_bfloat16* ash = (__nv_bfloat16*)(sm + O_AH);
    __nv_bfloat16* asl = (__nv_bfloat16*)(sm + O_AL);
    __nv_bfloat16* bsh = (__nv_bfloat16*)(sm + O_BH);
    __nv_bfloat16* bsl = (__nv_bfloat16*)(sm + O_BL);
    float*         br  = (float*)(sm + O_BR);

    const int tid = threadIdx.x;
    const int w = tid >> 5, mw = w >> 2, nw = w & 3;
    const int n0 = blockIdx.x * 128;
    const int m0 = blockIdx.y * 128;

    for (int i = tid; i < 2048; i += 256) br[i] = bo[n0 + (i & 127)];
    __syncthreads();

    FragC acc[4][2];
#pragma unroll
    for (int mi = 0; mi < 4; mi++)
#pragma unroll
        for (int ni = 0; ni < 2; ni++)
            wmma::load_matrix_sync(acc[mi][ni], br + nw*32 + ni*16, 128,
                                   wmma::mem_row_major);

    const uint32_t* aoh = (const uint32_t*)g_aoh;
    const uint32_t* aol = (const uint32_t*)g_aol;
    const uint32_t* woh = (const uint32_t*)g_woh;
    const uint32_t* wol = (const uint32_t*)g_wol;

    for (int kt = 0; kt < 16; kt++) {
        __syncthreads();
#pragma unroll 4
        for (int i = tid; i < 4096; i += 256) {
            int row = i >> 5, c = i & 31;
            uint32_t off = row * 36 + c;
            size_t ai = (size_t)(m0 + row) * 512 + kt * 32 + c;
            size_t bi = (size_t)(n0 + row) * 512 + kt * 32 + c;
            ((uint32_t*)ash)[off] = aoh[ai];
            ((uint32_t*)asl)[off] = aol[ai];
            ((uint32_t*)bsh)[off] = woh[bi];
            ((uint32_t*)bsl)[off] = wol[bi];
        }
        __syncthreads();

#pragma unroll
        for (int kc = 0; kc < 4; kc++) {
#pragma unroll
            for (int mi = 0; mi < 4; mi++) {
                FragA ah, al;
                wmma::load_matrix_sync(ah, ash + (mw*64 + mi*16)*LDA + kc*16, LDA);
                wmma::load_matrix_sync(al, asl + (mw*64 + mi*16)*LDA + kc*16, LDA);
#pragma unroll
                for (int ni = 0; ni < 2; ni++) {
                    FragBc bhf, blf;
                    wmma::load_matrix_sync(bhf, bsh + (nw*32 + ni*16)*LDA + kc*16, LDA);
                    wmma::load_matrix_sync(blf, bsl + (nw*32 + ni*16)*LDA + kc*16, LDA);
                    wmma::mma_sync(acc[mi][ni], ah, bhf, acc[mi][ni]);
                    wmma::mma_sync(acc[mi][ni], al, bhf, acc[mi][ni]);
                    wmma::mma_sync(acc[mi][ni], ah, blf, acc[mi][ni]);
                }
            }
        }
    }

#pragma unroll
    for (int mi = 0; mi < 4; mi++)
#pragma unroll
        for (int ni = 0; ni < 2; ni++)
            wmma::store_matrix_sync(
                out + (size_t)(m0 + mw*64 + mi*16) * DMODEL + n0 + nw*32 + ni*16,
                acc[mi][ni], DMODEL, wmma::mem_row_major);
}

// ---------------------------------------------------------------------------
extern "C" void kernel_launch(void* const* d_in, const int* in_sizes, int n_in,
                              void* d_out, int out_size)
{
    const float* q    = (const float*)d_in[0];
    const float* k    = (const float*)d_in[1];
    const float* v    = (const float*)d_in[2];
    const float* pt   = (const float*)d_in[3];
    const float* bias = (const float*)d_in[4];
    const float* W1   = (const float*)d_in[5];
    const float* b1   = (const float*)d_in[6];
    const float* w2   = (const float*)d_in[7];
    const float* b2   = (const float*)d_in[8];
    const float* Wo   = (const float*)d_in[9];
    const float* bo   = (const float*)d_in[10];

    float* graph_out = (float*)d_out;                              // [8,1024,1024]
    float* weights   = (float*)d_out + (size_t)Bb * Ll * DMODEL;   // [8,16,1024,1024]

    cudaFuncSetAttribute(attn_mma,
        cudaFuncAttributeMaxDynamicSharedMemorySize, ATTN2_SMEM);
    cudaFuncSetAttribute(outproj_wmma,
        cudaFuncAttributeMaxDynamicSharedMemorySize, OUT_SMEM);

    gate_kernel<<<BH * Ll / 8, 256>>>(pt, W1, b1, w2, b2);
    prep_wo_kernel<<<DMODEL * DMODEL / 256, 256>>>(Wo);
    attn_mma<<<dim3(Ll / 128, BH), 256, ATTN2_SMEM>>>(q, k, v, bias, weights);
    normalize_kernel<<<BH * Ll, 256>>>(weights);
    outproj_wmma<<<dim3(DMODEL / 128, Bb * Ll / 128), 256, OUT_SMEM>>>(bo, graph_out);
}

// round 10
// speedup vs baseline: 2.2336x; 1.0473x over previous
#include <cuda_runtime.h>
#include <cuda_bf16.h>
#include <cstdint>
#include <cstddef>

#define Bb 8
#define Hh 16
#define Ll 1024
#define Dd 64
#define BH (Bb*Hh)
#define DMODEL (Hh*Dd)
#define LDA 72                      // smem leading dim (bf16); row stride 144 B

// scratch (no allocations allowed)
__device__ float g_gate[BH*Ll];
__device__ __nv_bfloat16 g_aoh[(size_t)Bb*Ll*DMODEL];  // attnout hi [b*L+l][h*64+d]
__device__ __nv_bfloat16 g_aol[(size_t)Bb*Ll*DMODEL];  // attnout lo
__device__ __nv_bfloat16 g_woh[DMODEL*DMODEL];         // W_out hi [n][k]
__device__ __nv_bfloat16 g_wol[DMODEL*DMODEL];         // W_out lo

// ---- split helpers: x = hi(bf16) + lo(bf16) ----
__device__ __forceinline__ void split8(const float* x, uint4& hi, uint4& lo) {
    uint32_t hs[8], ls[8];
#pragma unroll
    for (int j = 0; j < 8; j++) {
        __nv_bfloat16 hb = __float2bfloat16(x[j]);
        __nv_bfloat16 lb = __float2bfloat16(x[j] - __bfloat162float(hb));
        hs[j] = (uint32_t)__bfloat16_as_ushort(hb);
        ls[j] = (uint32_t)__bfloat16_as_ushort(lb);
    }
    hi.x = hs[0]|(hs[1]<<16); hi.y = hs[2]|(hs[3]<<16);
    hi.z = hs[4]|(hs[5]<<16); hi.w = hs[6]|(hs[7]<<16);
    lo.x = ls[0]|(ls[1]<<16); lo.y = ls[2]|(ls[3]<<16);
    lo.z = ls[4]|(ls[5]<<16); lo.w = ls[6]|(ls[7]<<16);
}
__device__ __forceinline__ void split2(float a, float b, uint32_t& h, uint32_t& l) {
    __nv_bfloat16 ha = __float2bfloat16(a), hb = __float2bfloat16(b);
    __nv_bfloat16 la = __float2bfloat16(a - __bfloat162float(ha));
    __nv_bfloat16 lb = __float2bfloat16(b - __bfloat162float(hb));
    h = (uint32_t)__bfloat16_as_ushort(ha) | ((uint32_t)__bfloat16_as_ushort(hb) << 16);
    l = (uint32_t)__bfloat16_as_ushort(la) | ((uint32_t)__bfloat16_as_ushort(lb) << 16);
}

// ---- raw tensor-core / async primitives (baseline PTX, ok for compute_103) ----
__device__ __forceinline__ void ldsm4(uint32_t* r, uint32_t a) {
    asm volatile("ldmatrix.sync.aligned.m8n8.x4.shared.b16 {%0,%1,%2,%3}, [%4];"
        : "=r"(r[0]), "=r"(r[1]), "=r"(r[2]), "=r"(r[3]) : "r"(a));
}
__device__ __forceinline__ void ldsm2(uint32_t* r, uint32_t a) {
    asm volatile("ldmatrix.sync.aligned.m8n8.x2.shared.b16 {%0,%1}, [%2];"
        : "=r"(r[0]), "=r"(r[1]) : "r"(a));
}
__device__ __forceinline__ void ldsm2t(uint32_t* r, uint32_t a) {
    asm volatile("ldmatrix.sync.aligned.m8n8.x2.trans.shared.b16 {%0,%1}, [%2];"
        : "=r"(r[0]), "=r"(r[1]) : "r"(a));
}
__device__ __forceinline__ void mma16816(float* c, const uint32_t* a, const uint32_t* b) {
    asm volatile("mma.sync.aligned.m16n8k16.row.col.f32.bf16.bf16.f32 "
        "{%0,%1,%2,%3}, {%4,%5,%6,%7}, {%8,%9}, {%0,%1,%2,%3};"
        : "+f"(c[0]), "+f"(c[1]), "+f"(c[2]), "+f"(c[3])
        : "r"(a[0]), "r"(a[1]), "r"(a[2]), "r"(a[3]), "r"(b[0]), "r"(b[1]));
}
__device__ __forceinline__ uint32_t smem_u32(const void* p) {
    uint32_t a;
    asm("{ .reg .u64 t; cvta.to.shared.u64 t, %1; cvt.u32.u64 %0, t; }"
        : "=r"(a) : "l"(p));
    return a;
}
__device__ __forceinline__ void cp16(uint32_t dst, const void* src) {
    asm volatile("cp.async.cg.shared.global [%0], [%1], 16;"
        :: "r"(dst), "l"(src) : "memory");
}
#define CP_COMMIT() asm volatile("cp.async.commit_group;" ::: "memory")
#define CP_WAIT0()  asm volatile("cp.async.wait_group 0;" ::: "memory")
#define CP_WAIT1()  asm volatile("cp.async.wait_group 1;" ::: "memory")

// ---------------- K1: gate ----------------
__global__ __launch_bounds__(256) void gate_kernel(
    const float* __restrict__ pt, const float* __restrict__ W1,
    const float* __restrict__ b1, const float* __restrict__ w2,
    const float* __restrict__ b2)
{
    __shared__ float W1s[64][65];
    __shared__ float w2s[64], b1s[64], pts[8][64];
    const int tid = threadIdx.x;
    for (int i = tid; i < 64*64; i += 256) W1s[i >> 6][i & 63] = W1[i];
    if (tid < 64) { w2s[tid] = w2[tid]; b1s[tid] = b1[tid]; }
    __syncthreads();
    const int warp = tid >> 5, lane = tid & 31;
    const size_t row = (size_t)blockIdx.x * 8 + warp;
    const float* p = pt + row * Dd;
    pts[warp][lane] = p[lane];
    pts[warp][lane + 32] = p[lane + 32];
    __syncwarp();
    float a0 = 0.f, a1 = 0.f;
#pragma unroll
    for (int d = 0; d < 64; d++) {
        float x = pts[warp][d];
        a0 = fmaf(x, W1s[lane][d], a0);
        a1 = fmaf(x, W1s[lane + 32][d], a1);
    }
    float part = tanhf(a0 + b1s[lane]) * w2s[lane]
               + tanhf(a1 + b1s[lane + 32]) * w2s[lane + 32];
#pragma unroll
    for (int off = 16; off > 0; off >>= 1)
        part += __shfl_xor_sync(0xffffffffu, part, off);
    if (lane == 0)
        g_gate[row] = 1.0f / (1.0f + __expf(-(part + b2[0])));
}

// ---------------- prep: W_out -> bf16 hi/lo ----------------
__global__ __launch_bounds__(256) void prep_wo_kernel(const float* __restrict__ W)
{
    int i = blockIdx.x * 256 + threadIdx.x;
    float x = W[i];
    __nv_bfloat16 h = __float2bfloat16(x);
    g_woh[i] = h;
    g_wol[i] = __float2bfloat16(x - __bfloat162float(h));
}

// ---------------- attn: raw mma + cp.async bias prefetch + fused normalize ----
#define S_QH 0u          // 128 x 72 bf16 = 18432
#define S_QL 18432u
#define S_KH 36864u      // 64 x 72 bf16 = 9216
#define S_KL 46080u
#define S_VH 55296u
#define S_VL 64512u
#define S_GT 73728u      // 64 floats
#define S_BIAS 73984u    // 128 rows x 272 B = 34816 (also reused for inv[128])
#define ATTN3_SMEM 108800

__global__ __launch_bounds__(256, 2) void attn_mma(
    const float* __restrict__ q, const float* __restrict__ k,
    const float* __restrict__ v, const float* __restrict__ bias,
    float* __restrict__ wout)
{
    extern __shared__ char sm[];
    const uint32_t sb = smem_u32(sm);
    float* gt = (float*)(sm + S_GT);
    const float* bsm = (const float*)(sm + S_BIAS);

    const int tid = threadIdx.x, wp = tid >> 5, lane = tid & 31;
    const int g = lane >> 2, t = lane & 3;
    const int bh = blockIdx.y, b = bh >> 4, h = bh & 15;
    const int q0 = blockIdx.x * 128;
    const size_t kvb = (size_t)bh * Ll * Dd;
    const int r0 = wp * 16;

    // ---- Q tile: load, scale, split (once) ----
    {
        const float* qp = q + kvb + (size_t)q0 * Dd;
#pragma unroll
        for (int i = tid; i < 1024; i += 256) {
            int r = i >> 3, c8 = (i & 7) * 8;
            const float* s0 = qp + r * 64 + c8;
            float4 a = *(const float4*)s0, bq = *(const float4*)(s0 + 4);
            float x[8] = {a.x*.125f, a.y*.125f, a.z*.125f, a.w*.125f,
                          bq.x*.125f, bq.y*.125f, bq.z*.125f, bq.w*.125f};
            uint4 hi, lo; split8(x, hi, lo);
            *(uint4*)(sm + S_QH + r*144 + c8*2) = hi;
            *(uint4*)(sm + S_QL + r*144 + c8*2) = lo;
        }
    }

    // ldmatrix lane-address bases
    const int a_row = r0 + (lane & 7) + ((lane >> 3) & 1) * 8;  // A (Q) x4
    const int a_col = (lane >> 4) * 8;
    const uint32_t qhA = sb + S_QH + a_row*144 + a_col*2;
    const uint32_t qlA = sb + S_QL + a_row*144 + a_col*2;
    const int b_row = lane & 7;                                  // B (K) x2
    const int b_col = ((lane >> 3) & 1) * 8;
    const uint32_t khB = sb + S_KH + b_row*144 + b_col*2;
    const uint32_t klB = sb + S_KL + b_row*144 + b_col*2;
    const int v_row = (lane & 7) + ((lane >> 3) & 1) * 8;        // B (V) x2 trans
    const uint32_t vhB = sb + S_VH + v_row*144;
    const uint32_t vlB = sb + S_VL + v_row*144;

    float oacc[8][4];
#pragma unroll
    for (int c = 0; c < 8; c++)
#pragma unroll
        for (int j = 0; j < 4; j++) oacc[c][j] = 0.f;
    float rs0 = 0.f, rs1 = 0.f;

    const size_t rowg  = (size_t)bh * Ll * Ll + (size_t)(q0 + r0 + g) * Ll;
    const size_t rowg8 = rowg + 8 * (size_t)Ll;
    const uint32_t brow0 = (uint32_t)(r0 + g) * 68;
    const uint32_t brow8 = brow0 + 8 * 68;

    for (int kt = 0; kt < 16; kt++) {
        // ---- bias tile cp.async prefetch (issued first: latency hides under KV+QK) ----
        {
            const float* bsrc = bias + (size_t)bh * Ll * Ll + (size_t)q0 * Ll + kt * 64;
#pragma unroll
            for (int j = 0; j < 8; j++) {
                int ci = tid + j * 256;          // 0..2047 (128 rows x 16 chunks)
                int row = ci >> 4, c16 = ci & 15;
                cp16(sb + S_BIAS + row * 272 + c16 * 16,
                     bsrc + (size_t)row * Ll + c16 * 4);
            }
            CP_COMMIT();
        }

        // ---- K/V tile: load + split ----
        {
            const float* kp = k + kvb + (size_t)kt * 64 * Dd;
            const float* vp = v + kvb + (size_t)kt * 64 * Dd;
#pragma unroll
            for (int i = tid; i < 512; i += 256) {
                int r = i >> 3, c8 = (i & 7) * 8;
                const float* s0 = kp + r * 64 + c8;
                float4 a = *(const float4*)s0, bq = *(const float4*)(s0 + 4);
                float x[8] = {a.x, a.y, a.z, a.w, bq.x, bq.y, bq.z, bq.w};
                uint4 hi, lo; split8(x, hi, lo);
                *(uint4*)(sm + S_KH + r*144 + c8*2) = hi;
                *(uint4*)(sm + S_KL + r*144 + c8*2) = lo;
                const float* t0 = vp + r * 64 + c8;
                float4 va = *(const float4*)t0, vb = *(const float4*)(t0 + 4);
                float y[8] = {va.x, va.y, va.z, va.w, vb.x, vb.y, vb.z, vb.w};
                split8(y, hi, lo);
                *(uint4*)(sm + S_VH + r*144 + c8*2) = hi;
                *(uint4*)(sm + S_VL + r*144 + c8*2) = lo;
            }
            if (tid < 64)
                gt[tid] = __ldg(&g_gate[(size_t)bh * Ll + kt * 64 + tid]);
        }
        __syncthreads();

        // ---- QK^T: sacc = (Qh+Ql)K^T 3-term, all in regs ----
        float sacc[8][4];
#pragma unroll
        for (int c = 0; c < 8; c++)
#pragma unroll
            for (int j = 0; j < 4; j++) sacc[c][j] = 0.f;

#pragma unroll
        for (int kc = 0; kc < 4; kc++) {
            uint32_t ah[4], al[4];
            ldsm4(ah, qhA + kc*32);
            ldsm4(al, qlA + kc*32);
#pragma unroll
            for (int c = 0; c < 8; c++) {
                uint32_t bh2[2], bl2[2];
                ldsm2(bh2, khB + c*1152 + kc*32);
                ldsm2(bl2, klB + c*1152 + kc*32);
                mma16816(sacc[c], ah, bh2);
                mma16816(sacc[c], al, bh2);
                mma16816(sacc[c], ah, bl2);
            }
        }

        // ---- bias now resident in smem ----
        CP_WAIT0();
        __syncthreads();

        // ---- in-register epilogue: +bias(smem), exp, rsum, *gate, STG weights ----
        {
            float* wg  = wout + rowg  + kt*64 + 2*t;
            float* wg8 = wout + rowg8 + kt*64 + 2*t;
#pragma unroll
            for (int c = 0; c < 8; c++) {
                float2 bv0 = *(const float2*)(bsm + brow0 + 2*t + 8*c);
                float2 bv1 = *(const float2*)(bsm + brow8 + 2*t + 8*c);
                float e00 = __expf(sacc[c][0] + bv0.x);
                float e01 = __expf(sacc[c][1] + bv0.y);
                float e10 = __expf(sacc[c][2] + bv1.x);
                float e11 = __expf(sacc[c][3] + bv1.y);
                rs0 += e00 + e01;
                rs1 += e10 + e11;
                float2 gv = *(float2*)(gt + c*8 + 2*t);
                float w00 = e00 * gv.x, w01 = e01 * gv.y;
                float w10 = e10 * gv.x, w11 = e11 * gv.y;
                float2 o0 = {w00, w01}, o1 = {w10, w11};
                *(float2*)(wg  + c*8) = o0;
                *(float2*)(wg8 + c*8) = o1;
                sacc[c][0] = w00; sacc[c][1] = w01;
                sacc[c][2] = w10; sacc[c][3] = w11;
            }
        }

        // ---- P·V: O += (Ph+Pl)(Vh+Vl) 3-term; P fragments built in-register ----
#pragma unroll
        for (int kc = 0; kc < 4; kc++) {
            uint32_t ph[4], pl[4];
            split2(sacc[2*kc][0],   sacc[2*kc][1],   ph[0], pl[0]);
            split2(sacc[2*kc][2],   sacc[2*kc][3],   ph[1], pl[1]);
            split2(sacc[2*kc+1][0], sacc[2*kc+1][1], ph[2], pl[2]);
            split2(sacc[2*kc+1][2], sacc[2*kc+1][3], ph[3], pl[3]);
#pragma unroll
            for (int cd = 0; cd < 8; cd++) {
                uint32_t vh2[2], vl2[2];
                ldsm2t(vh2, vhB + kc*2304 + cd*16);
                ldsm2t(vl2, vlB + kc*2304 + cd*16);
                mma16816(oacc[cd], ph, vh2);
                mma16816(oacc[cd], pl, vh2);
                mma16816(oacc[cd], ph, vl2);
            }
        }
        __syncthreads();
    }

    // ---- rowsum reduce (within quad), normalized O -> g_ao hi/lo ----
    rs0 += __shfl_xor_sync(0xffffffffu, rs0, 1);
    rs0 += __shfl_xor_sync(0xffffffffu, rs0, 2);
    rs1 += __shfl_xor_sync(0xffffffffu, rs1, 1);
    rs1 += __shfl_xor_sync(0xffffffffu, rs1, 2);
    const float inv0 = 1.0f / rs0, inv1 = 1.0f / rs1;
    {
        const size_t m0r = (size_t)b * 1024 + q0 + r0 + g;
        uint32_t* dh0 = (uint32_t*)g_aoh + m0r * (DMODEL/2) + h * 32;
        uint32_t* dl0 = (uint32_t*)g_aol + m0r * (DMODEL/2) + h * 32;
        uint32_t* dh8 = dh0 + 8 * (DMODEL/2);
        uint32_t* dl8 = dl0 + 8 * (DMODEL/2);
#pragma unroll
        for (int cd = 0; cd < 8; cd++) {
            uint32_t hh, ll;
            split2(oacc[cd][0] * inv0, oacc[cd][1] * inv0, hh, ll);
            dh0[cd*4 + t] = hh; dl0[cd*4 + t] = ll;
            split2(oacc[cd][2] * inv1, oacc[cd][3] * inv1, hh, ll);
            dh8[cd*4 + t] = hh; dl8[cd*4 + t] = ll;
        }
    }

    // ---- fused normalize: rescale this CTA's 128x1024 weight rows ----
    {
        float* invs = (float*)(sm + S_BIAS);   // reuse bias buffer (reads done)
        if (t == 0) {
            invs[r0 + g]     = inv0;
            invs[r0 + g + 8] = inv1;
        }
        __syncthreads();
        float* wbase = wout + (size_t)bh * Ll * Ll + (size_t)q0 * Ll;
#pragma unroll 4
        for (int j = 0; j < 128; j++) {
            float inv = invs[j];
            float4* p = (float4*)(wbase + (size_t)j * Ll) + tid;
            float4 x = *p;
            x.x *= inv; x.y *= inv; x.z *= inv; x.w *= inv;
            *p = x;
        }
    }
}

// ---------------- outproj: raw mma + 2-stage cp.async pipeline ----------------
#define OP_AH 0u
#define OP_AL 18432u
#define OP_BH 36864u
#define OP_BL 55296u
#define OP_STAGE 73728u
#define OP_BO (2u*OP_STAGE)          // 147456: 128 floats bias
#define OUT2_SMEM 147968

__device__ __forceinline__ void op_issue(uint32_t sbase, int m0, int n0,
                                         int kt, int tid) {
#pragma unroll
    for (int j = 0; j < 4; j++) {
        int ci = tid + j * 256;                 // 0..1023 per-array chunk
        int row = ci >> 3, c16 = ci & 7;
        uint32_t doff = (uint32_t)row * 144 + c16 * 16;
        size_t aoff = ((size_t)(m0 + row) * 512 + kt * 32 + c16 * 4) * 4;
        size_t boff = ((size_t)(n0 + row) * 512 + kt * 32 + c16 * 4) * 4;
        cp16(sbase + OP_AH + doff, (const char*)g_aoh + aoff);
        cp16(sbase + OP_AL + doff, (const char*)g_aol + aoff);
        cp16(sbase + OP_BH + doff, (const char*)g_woh + boff);
        cp16(sbase + OP_BL + doff, (const char*)g_wol + boff);
    }
}

__global__ __launch_bounds__(256, 1) void outproj_mma(
    const float* __restrict__ bo, float* __restrict__ out)
{
    extern __shared__ char sm[];
    const uint32_t sb = smem_u32(sm);
    const int tid = threadIdx.x, wp = tid >> 5, lane = tid & 31;
    const int g = lane >> 2, t = lane & 3;
    const int mw = wp >> 2, nw = wp & 3;
    const int n0 = blockIdx.x * 128, m0 = blockIdx.y * 128;

    float* bos = (float*)(sm + OP_BO);
    if (tid < 128) bos[tid] = bo[n0 + tid];

    op_issue(sb, m0, n0, 0, tid);
    CP_COMMIT();

    float acc[4][4][4];
#pragma unroll
    for (int mi = 0; mi < 4; mi++)
#pragma unroll
        for (int ni = 0; ni < 4; ni++)
#pragma unroll
            for (int j = 0; j < 4; j++) acc[mi][ni][j] = 0.f;

    // ldmatrix lane-address bases (within stage)
    const uint32_t aOff = (uint32_t)(mw*64 + (lane & 7) + ((lane >> 3) & 1) * 8) * 144
                        + (lane >> 4) * 16;
    const uint32_t bOff = (uint32_t)(nw*32 + (lane & 7)) * 144
                        + ((lane >> 3) & 1) * 16;

    for (int kt = 0; kt < 16; kt++) {
        const uint32_t stg = sb + (uint32_t)(kt & 1) * OP_STAGE;
        if (kt < 15) {
            op_issue(sb + (uint32_t)((kt + 1) & 1) * OP_STAGE, m0, n0, kt + 1, tid);
            CP_COMMIT();
            CP_WAIT1();
        } else {
            CP_WAIT0();
        }
        __syncthreads();

#pragma unroll
        for (int kc = 0; kc < 4; kc++) {
            uint32_t bfh[4][2], bfl[4][2];
#pragma unroll
            for (int ni = 0; ni < 4; ni++) {
                ldsm2(bfh[ni], stg + OP_BH + bOff + ni*1152 + kc*32);
                ldsm2(bfl[ni], stg + OP_BL + bOff + ni*1152 + kc*32);
            }
#pragma unroll
            for (int mi = 0; mi < 4; mi++) {
                uint32_t ah[4], al[4];
                ldsm4(ah, stg + OP_AH + aOff + mi*2304 + kc*32);
                ldsm4(al, stg + OP_AL + aOff + mi*2304 + kc*32);
#pragma unroll
                for (int ni = 0; ni < 4; ni++) {
                    mma16816(acc[mi][ni], ah, bfh[ni]);
                    mma16816(acc[mi][ni], al, bfh[ni]);
                    mma16816(acc[mi][ni], ah, bfl[ni]);
                }
            }
        }
        __syncthreads();
    }

    // epilogue: + bias, store float2 pairs
#pragma unroll
    for (int mi = 0; mi < 4; mi++) {
        const int row0 = m0 + mw*64 + mi*16 + g;
#pragma unroll
        for (int ni = 0; ni < 4; ni++) {
            const int col = nw*32 + ni*8 + 2*t;
            float2 b2 = *(const float2*)(bos + col);
            float2 o0 = {acc[mi][ni][0] + b2.x, acc[mi][ni][1] + b2.y};
            float2 o1 = {acc[mi][ni][2] + b2.x, acc[mi][ni][3] + b2.y};
            *(float2*)(out + (size_t)row0 * DMODEL + n0 + col) = o0;
            *(float2*)(out + (size_t)(row0 + 8) * DMODEL + n0 + col) = o1;
        }
    }
}

// ---------------------------------------------------------------------------
extern "C" void kernel_launch(void* const* d_in, const int* in_sizes, int n_in,
                              void* d_out, int out_size)
{
    const float* q    = (const float*)d_in[0];
    const float* k    = (const float*)d_in[1];
    const float* v    = (const float*)d_in[2];
    const float* pt   = (const float*)d_in[3];
    const float* bias = (const float*)d_in[4];
    const float* W1   = (const float*)d_in[5];
    const float* b1   = (const float*)d_in[6];
    const float* w2   = (const float*)d_in[7];
    const float* b2   = (const float*)d_in[8];
    const float* Wo   = (const float*)d_in[9];
    const float* bo   = (const float*)d_in[10];

    float* graph_out = (float*)d_out;                              // [8,1024,1024]
    float* weights   = (float*)d_out + (size_t)Bb * Ll * DMODEL;   // [8,16,1024,1024]

    cudaFuncSetAttribute(attn_mma,
        cudaFuncAttributeMaxDynamicSharedMemorySize, ATTN3_SMEM);
    cudaFuncSetAttribute(outproj_mma,
        cudaFuncAttributeMaxDynamicSharedMemorySize, OUT2_SMEM);

    gate_kernel<<<BH * Ll / 8, 256>>>(pt, W1, b1, w2, b2);
    prep_wo_kernel<<<DMODEL * DMODEL / 256, 256>>>(Wo);
    attn_mma<<<dim3(Ll / 128, BH), 256, ATTN3_SMEM>>>(q, k, v, bias, weights);
    outproj_mma<<<dim3(DMODEL / 128, Bb * Ll / 128), 256, OUT2_SMEM>>>(bo, graph_out);
}

// round 13
// speedup vs baseline: 2.2947x; 1.0273x over previous
#include <cuda_runtime.h>
#include <cuda_bf16.h>
#include <cstdint>
#include <cstddef>

#define Bb 8
#define Hh 16
#define Ll 1024
#define Dd 64
#define BH (Bb*Hh)
#define DMODEL (Hh*Dd)

// scratch (no allocations allowed)
__device__ float g_gate[BH*Ll];
__device__ __nv_bfloat16 g_aoh[(size_t)Bb*Ll*DMODEL];  // attnout hi [b*L+l][h*64+d]
__device__ __nv_bfloat16 g_aol[(size_t)Bb*Ll*DMODEL];  // attnout lo
__device__ __nv_bfloat16 g_woh[DMODEL*DMODEL];         // W_out hi [n][k]
__device__ __nv_bfloat16 g_wol[DMODEL*DMODEL];         // W_out lo

// ---- split helpers ----
__device__ __forceinline__ void split8(const float* x, uint4& hi, uint4& lo) {
    uint32_t hs[8], ls[8];
#pragma unroll
    for (int j = 0; j < 8; j++) {
        __nv_bfloat16 hb = __float2bfloat16(x[j]);
        __nv_bfloat16 lb = __float2bfloat16(x[j] - __bfloat162float(hb));
        hs[j] = (uint32_t)__bfloat16_as_ushort(hb);
        ls[j] = (uint32_t)__bfloat16_as_ushort(lb);
    }
    hi.x = hs[0]|(hs[1]<<16); hi.y = hs[2]|(hs[3]<<16);
    hi.z = hs[4]|(hs[5]<<16); hi.w = hs[6]|(hs[7]<<16);
    lo.x = ls[0]|(ls[1]<<16); lo.y = ls[2]|(ls[3]<<16);
    lo.z = ls[4]|(ls[5]<<16); lo.w = ls[6]|(ls[7]<<16);
}
__device__ __forceinline__ void split2(float a, float b, uint32_t& h, uint32_t& l) {
    __nv_bfloat16 ha = __float2bfloat16(a), hb = __float2bfloat16(b);
    __nv_bfloat16 la = __float2bfloat16(a - __bfloat162float(ha));
    __nv_bfloat16 lb = __float2bfloat16(b - __bfloat162float(hb));
    h = (uint32_t)__bfloat16_as_ushort(ha) | ((uint32_t)__bfloat16_as_ushort(hb) << 16);
    l = (uint32_t)__bfloat16_as_ushort(la) | ((uint32_t)__bfloat16_as_ushort(lb) << 16);
}

// ---- raw tensor-core / async primitives ----
__device__ __forceinline__ void ldsm4(uint32_t* r, uint32_t a) {
    asm volatile("ldmatrix.sync.aligned.m8n8.x4.shared.b16 {%0,%1,%2,%3}, [%4];"
        : "=r"(r[0]), "=r"(r[1]), "=r"(r[2]), "=r"(r[3]) : "r"(a));
}
__device__ __forceinline__ void ldsm2(uint32_t* r, uint32_t a) {
    asm volatile("ldmatrix.sync.aligned.m8n8.x2.shared.b16 {%0,%1}, [%2];"
        : "=r"(r[0]), "=r"(r[1]) : "r"(a));
}
__device__ __forceinline__ void ldsm2t(uint32_t* r, uint32_t a) {
    asm volatile("ldmatrix.sync.aligned.m8n8.x2.trans.shared.b16 {%0,%1}, [%2];"
        : "=r"(r[0]), "=r"(r[1]) : "r"(a));
}
__device__ __forceinline__ void mma16816(float* c, const uint32_t* a, const uint32_t* b) {
    asm volatile("mma.sync.aligned.m16n8k16.row.col.f32.bf16.bf16.f32 "
        "{%0,%1,%2,%3}, {%4,%5,%6,%7}, {%8,%9}, {%0,%1,%2,%3};"
        : "+f"(c[0]), "+f"(c[1]), "+f"(c[2]), "+f"(c[3])
        : "r"(a[0]), "r"(a[1]), "r"(a[2]), "r"(a[3]), "r"(b[0]), "r"(b[1]));
}
__device__ __forceinline__ uint32_t smem_u32(const void* p) {
    uint32_t a;
    asm("{ .reg .u64 t; cvta.to.shared.u64 t, %1; cvt.u32.u64 %0, t; }"
        : "=r"(a) : "l"(p));
    return a;
}
__device__ __forceinline__ void cp16(uint32_t dst, const void* src) {
    asm volatile("cp.async.cg.shared.global [%0], [%1], 16;"
        :: "r"(dst), "l"(src) : "memory");
}
#define CP_COMMIT() asm volatile("cp.async.commit_group;" ::: "memory")
#define CP_WAIT0()  asm volatile("cp.async.wait_group 0;" ::: "memory")
#define CP_WAIT1()  asm volatile("cp.async.wait_group 1;" ::: "memory")

// ---------------- K1: gate ----------------
__global__ __launch_bounds__(256) void gate_kernel(
    const float* __restrict__ pt, const float* __restrict__ W1,
    const float* __restrict__ b1, const float* __restrict__ w2,
    const float* __restrict__ b2)
{
    __shared__ float W1s[64][65];
    __shared__ float w2s[64], b1s[64], pts[8][64];
    const int tid = threadIdx.x;
    for (int i = tid; i < 64*64; i += 256) W1s[i >> 6][i & 63] = W1[i];
    if (tid < 64) { w2s[tid] = w2[tid]; b1s[tid] = b1[tid]; }
    __syncthreads();
    const int warp = tid >> 5, lane = tid & 31;
    const size_t row = (size_t)blockIdx.x * 8 + warp;
    const float* p = pt + row * Dd;
    pts[warp][lane] = p[lane];
    pts[warp][lane + 32] = p[lane + 32];
    __syncwarp();
    float a0 = 0.f, a1 = 0.f;
#pragma unroll
    for (int d = 0; d < 64; d++) {
        float x = pts[warp][d];
        a0 = fmaf(x, W1s[lane][d], a0);
        a1 = fmaf(x, W1s[lane + 32][d], a1);
    }
    float part = tanhf(a0 + b1s[lane]) * w2s[lane]
               + tanhf(a1 + b1s[lane + 32]) * w2s[lane + 32];
#pragma unroll
    for (int off = 16; off > 0; off >>= 1)
        part += __shfl_xor_sync(0xffffffffu, part, off);
    if (lane == 0)
        g_gate[row] = 1.0f / (1.0f + __expf(-(part + b2[0])));
}

// ---------------- prep: W_out -> bf16 hi/lo ----------------
__global__ __launch_bounds__(256) void prep_wo_kernel(const float* __restrict__ W)
{
    int i = blockIdx.x * 256 + threadIdx.x;
    float x = W[i];
    __nv_bfloat16 h = __float2bfloat16(x);
    g_woh[i] = h;
    g_wol[i] = __float2bfloat16(x - __bfloat162float(h));
}

// ---------------- attn: reg-resident Q, cp.async KV+bias pipeline ----------
// smem: [0,36864) stage (Q split at init, then raw K@0/V@16384 fp32)
//       [36864..73728) K/V split hi/lo (each 9216, rows 144 B)
//       [73728,73984) gate 64 f32
//       [73984,108800) bias 128 x 272 B (reused as inv[128] at tail)
#define S_STG 0u
#define S_KH 36864u
#define S_KL 46080u
#define S_VH 55296u
#define S_VL 64512u
#define S_GT 73728u
#define S_BIAS 73984u
#define ATTN3_SMEM 108800

__global__ __launch_bounds__(256, 2) void attn_mma(
    const float* __restrict__ q, const float* __restrict__ k,
    const float* __restrict__ v, const float* __restrict__ bias,
    float* __restrict__ wout)
{
    extern __shared__ char sm[];
    const uint32_t sb = smem_u32(sm);
    float* gt = (float*)(sm + S_GT);
    const float* bsm = (const float*)(sm + S_BIAS);

    const int tid = threadIdx.x, wp = tid >> 5, lane = tid & 31;
    const int g = lane >> 2, t = lane & 3;
    const int bh = blockIdx.y, b = bh >> 4, h = bh & 15;
    const int q0 = blockIdx.x * 128;
    const size_t kvb = (size_t)bh * Ll * Dd;
    const int r0 = wp * 16;

    // ---- Q tile: load+scale+split into stage region, then frags -> regs ----
    {
        const float* qp = q + kvb + (size_t)q0 * Dd;
#pragma unroll
        for (int i = tid; i < 1024; i += 256) {
            int r = i >> 3, c8 = (i & 7) * 8;
            const float* s0 = qp + r * 64 + c8;
            float4 a = *(const float4*)s0, bq = *(const float4*)(s0 + 4);
            float x[8] = {a.x*.125f, a.y*.125f, a.z*.125f, a.w*.125f,
                          bq.x*.125f, bq.y*.125f, bq.z*.125f, bq.w*.125f};
            uint4 hi, lo; split8(x, hi, lo);
            *(uint4*)(sm + S_STG + r*144 + c8*2) = hi;
            *(uint4*)(sm + S_STG + 18432 + r*144 + c8*2) = lo;
        }
    }
    __syncthreads();
    uint32_t qfh[4][4], qfl[4][4];
    {
        const int a_row = r0 + (lane & 7) + ((lane >> 3) & 1) * 8;
        const int a_col = (lane >> 4) * 8;
        const uint32_t qhA = sb + S_STG + a_row*144 + a_col*2;
        const uint32_t qlA = qhA + 18432;
#pragma unroll
        for (int kc = 0; kc < 4; kc++) {
            ldsm4(qfh[kc], qhA + kc*32);
            ldsm4(qfl[kc], qlA + kc*32);
        }
    }
    __syncthreads();   // frags in regs; stage region now free for KV

    // ldmatrix lane bases for K (B, x2) and V (B, x2 trans)
    const int b_row = lane & 7;
    const int b_col = ((lane >> 3) & 1) * 8;
    const uint32_t khB = sb + S_KH + b_row*144 + b_col*2;
    const uint32_t klB = sb + S_KL + b_row*144 + b_col*2;
    const int v_row = (lane & 7) + ((lane >> 3) & 1) * 8;
    const uint32_t vhB = sb + S_VH + v_row*144;
    const uint32_t vlB = sb + S_VL + v_row*144;

    float oacc[8][4];
#pragma unroll
    for (int c = 0; c < 8; c++)
#pragma unroll
        for (int j = 0; j < 4; j++) oacc[c][j] = 0.f;
    float rs0 = 0.f, rs1 = 0.f;

    const size_t rowg  = (size_t)bh * Ll * Ll + (size_t)(q0 + r0 + g) * Ll;
    const size_t rowg8 = rowg + 8 * (size_t)Ll;
    const uint32_t brow0 = (uint32_t)(r0 + g) * 68;
    const uint32_t brow8 = brow0 + 8 * 68;
    const float* bias_base = bias + (size_t)bh * Ll * Ll + (size_t)q0 * Ll;

    // preloop: KV(0) group, then bias(0) group
    {
        const float* kp = k + kvb;
        const float* vp = v + kvb;
#pragma unroll
        for (int j = 0; j < 4; j++) {
            int ci = tid + j * 256;
            int row = ci >> 4, c16 = ci & 15;
            cp16(sb + S_STG + row*256 + c16*16, kp + row*64 + c16*4);
            cp16(sb + S_STG + 16384 + row*256 + c16*16, vp + row*64 + c16*4);
        }
        CP_COMMIT();
#pragma unroll
        for (int j = 0; j < 8; j++) {
            int ci = tid + j * 256;
            int row = ci >> 4, c16 = ci & 15;
            cp16(sb + S_BIAS + row*272 + c16*16,
                 bias_base + (size_t)row * Ll + c16 * 4);
        }
        CP_COMMIT();
    }

    for (int kt = 0; kt < 16; kt++) {
        CP_WAIT1();          // KV(kt) resident (bias(kt) may be in flight)
        __syncthreads();

        // ---- split staging (fp32) -> K/V hi/lo ----
#pragma unroll
        for (int i = tid; i < 512; i += 256) {
            int r = i >> 3, c8 = (i & 7) * 8;
            const float* s0 = (const float*)(sm + S_STG + r*256 + c8*4);
            float x[8] = {s0[0], s0[1], s0[2], s0[3], s0[4], s0[5], s0[6], s0[7]};
            uint4 hi, lo; split8(x, hi, lo);
            *(uint4*)(sm + S_KH + r*144 + c8*2) = hi;
            *(uint4*)(sm + S_KL + r*144 + c8*2) = lo;
            const float* t0 = (const float*)(sm + S_STG + 16384 + r*256 + c8*4);
            float y[8] = {t0[0], t0[1], t0[2], t0[3], t0[4], t0[5], t0[6], t0[7]};
            split8(y, hi, lo);
            *(uint4*)(sm + S_VH + r*144 + c8*2) = hi;
            *(uint4*)(sm + S_VL + r*144 + c8*2) = lo;
        }
        if (tid < 64)
            gt[tid] = __ldg(&g_gate[(size_t)bh * Ll + kt * 64 + tid]);
        __syncthreads();     // split smem ready; staging consumed

        // ---- prefetch KV(kt+1) into staging ----
        if (kt < 15) {
            const float* kp = k + kvb + (size_t)(kt + 1) * 64 * Dd;
            const float* vp = v + kvb + (size_t)(kt + 1) * 64 * Dd;
#pragma unroll
            for (int j = 0; j < 4; j++) {
                int ci = tid + j * 256;
                int row = ci >> 4, c16 = ci & 15;
                cp16(sb + S_STG + row*256 + c16*16, kp + row*64 + c16*4);
                cp16(sb + S_STG + 16384 + row*256 + c16*16, vp + row*64 + c16*4);
            }
            CP_COMMIT();
        }

        // ---- QK^T: 3-term, Q from regs ----
        float sacc[8][4];
#pragma unroll
        for (int c = 0; c < 8; c++)
#pragma unroll
            for (int j = 0; j < 4; j++) sacc[c][j] = 0.f;
#pragma unroll
        for (int kc = 0; kc < 4; kc++) {
#pragma unroll
            for (int c = 0; c < 8; c++) {
                uint32_t bh2[2], bl2[2];
                ldsm2(bh2, khB + c*1152 + kc*32);
                ldsm2(bl2, klB + c*1152 + kc*32);
                mma16816(sacc[c], qfh[kc], bh2);
                mma16816(sacc[c], qfl[kc], bh2);
                mma16816(sacc[c], qfh[kc], bl2);
            }
        }

        // ---- bias(kt) resident (leave KV(kt+1) in flight) ----
        if (kt < 15) CP_WAIT1(); else CP_WAIT0();
        __syncthreads();

        // ---- in-register epilogue ----
        {
            float* wg  = wout + rowg  + kt*64 + 2*t;
            float* wg8 = wout + rowg8 + kt*64 + 2*t;
#pragma unroll
            for (int c = 0; c < 8; c++) {
                float2 bv0 = *(const float2*)(bsm + brow0 + 2*t + 8*c);
                float2 bv1 = *(const float2*)(bsm + brow8 + 2*t + 8*c);
                float e00 = __expf(sacc[c][0] + bv0.x);
                float e01 = __expf(sacc[c][1] + bv0.y);
                float e10 = __expf(sacc[c][2] + bv1.x);
                float e11 = __expf(sacc[c][3] + bv1.y);
                rs0 += e00 + e01;
                rs1 += e10 + e11;
                float2 gv = *(float2*)(gt + c*8 + 2*t);
                float w00 = e00 * gv.x, w01 = e01 * gv.y;
                float w10 = e10 * gv.x, w11 = e11 * gv.y;
                float2 o0 = {w00, w01}, o1 = {w10, w11};
                *(float2*)(wg  + c*8) = o0;
                *(float2*)(wg8 + c*8) = o1;
                sacc[c][0] = w00; sacc[c][1] = w01;
                sacc[c][2] = w10; sacc[c][3] = w11;
            }
        }

        // ---- P·V: 3-term ----
#pragma unroll
        for (int kc = 0; kc < 4; kc++) {
            uint32_t ph[4], pl[4];
            split2(sacc[2*kc][0],   sacc[2*kc][1],   ph[0], pl[0]);
            split2(sacc[2*kc][2],   sacc[2*kc][3],   ph[1], pl[1]);
            split2(sacc[2*kc+1][0], sacc[2*kc+1][1], ph[2], pl[2]);
            split2(sacc[2*kc+1][2], sacc[2*kc+1][3], ph[3], pl[3]);
#pragma unroll
            for (int cd = 0; cd < 8; cd++) {
                uint32_t vh2[2], vl2[2];
                ldsm2t(vh2, vhB + kc*2304 + cd*16);
                ldsm2t(vl2, vlB + kc*2304 + cd*16);
                mma16816(oacc[cd], ph, vh2);
                mma16816(oacc[cd], pl, vh2);
                mma16816(oacc[cd], ph, vl2);
            }
        }
        __syncthreads();     // bias reads done; V reads done

        // ---- prefetch bias(kt+1) ----
        if (kt < 15) {
#pragma unroll
            for (int j = 0; j < 8; j++) {
                int ci = tid + j * 256;
                int row = ci >> 4, c16 = ci & 15;
                cp16(sb + S_BIAS + row*272 + c16*16,
                     bias_base + (size_t)row * Ll + (kt + 1) * 64 + c16 * 4);
            }
            CP_COMMIT();
        }
    }

    // ---- rowsum reduce, normalized O -> g_ao hi/lo ----
    rs0 += __shfl_xor_sync(0xffffffffu, rs0, 1);
    rs0 += __shfl_xor_sync(0xffffffffu, rs0, 2);
    rs1 += __shfl_xor_sync(0xffffffffu, rs1, 1);
    rs1 += __shfl_xor_sync(0xffffffffu, rs1, 2);
    const float inv0 = 1.0f / rs0, inv1 = 1.0f / rs1;
    {
        const size_t m0r = (size_t)b * 1024 + q0 + r0 + g;
        uint32_t* dh0 = (uint32_t*)g_aoh + m0r * (DMODEL/2) + h * 32;
        uint32_t* dl0 = (uint32_t*)g_aol + m0r * (DMODEL/2) + h * 32;
        uint32_t* dh8 = dh0 + 8 * (DMODEL/2);
        uint32_t* dl8 = dl0 + 8 * (DMODEL/2);
#pragma unroll
        for (int cd = 0; cd < 8; cd++) {
            uint32_t hh, ll;
            split2(oacc[cd][0] * inv0, oacc[cd][1] * inv0, hh, ll);
            dh0[cd*4 + t] = hh; dl0[cd*4 + t] = ll;
            split2(oacc[cd][2] * inv1, oacc[cd][3] * inv1, hh, ll);
            dh8[cd*4 + t] = hh; dl8[cd*4 + t] = ll;
        }
    }

    // ---- fused normalize of this CTA's weight rows ----
    {
        float* invs = (float*)(sm + S_BIAS);
        if (t == 0) {
            invs[r0 + g]     = inv0;
            invs[r0 + g + 8] = inv1;
        }
        __syncthreads();
        float* wbase = wout + (size_t)bh * Ll * Ll + (size_t)q0 * Ll;
#pragma unroll 4
        for (int j = 0; j < 128; j++) {
            float inv = invs[j];
            float4* p = (float4*)(wbase + (size_t)j * Ll) + tid;
            float4 x = *p;
            x.x *= inv; x.y *= inv; x.z *= inv; x.w *= inv;
            *p = x;
        }
    }
}

// ---------------- outproj: 128x64 tiles, 2-stage cp.async, 2 CTAs/SM --------
#define OA_H 0u           // 128 x 144
#define OA_L 18432u
#define OB_H 36864u       // 64 x 144
#define OB_L 46080u
#define OP_STAGE 55296u
#define OP_BO (2u*OP_STAGE)     // 110592: 64 floats bias
#define OUT3_SMEM 110848

__device__ __forceinline__ void op_issue(uint32_t st, int m0, int n0,
                                         int kt, int tid) {
#pragma unroll
    for (int j = 0; j < 4; j++) {
        int ci = tid + j * 256;                 // 0..1023 (A: 128 rows x 8)
        int row = ci >> 3, c16 = ci & 7;
        uint32_t doff = (uint32_t)row * 144 + c16 * 16;
        size_t aoff = ((size_t)(m0 + row) * 512 + kt * 32 + c16 * 4) * 4;
        cp16(st + OA_H + doff, (const char*)g_aoh + aoff);
        cp16(st + OA_L + doff, (const char*)g_aol + aoff);
    }
#pragma unroll
    for (int j = 0; j < 2; j++) {
        int ci = tid + j * 256;                 // 0..511 (B: 64 rows x 8)
        int row = ci >> 3, c16 = ci & 7;
        uint32_t doff = (uint32_t)row * 144 + c16 * 16;
        size_t boff = ((size_t)(n0 + row) * 512 + kt * 32 + c16 * 4) * 4;
        cp16(st + OB_H + doff, (const char*)g_woh + boff);
        cp16(st + OB_L + doff, (const char*)g_wol + boff);
    }
}

__global__ __launch_bounds__(256, 2) void outproj_mma(
    const float* __restrict__ bo, float* __restrict__ out)
{
    extern __shared__ char sm[];
    const uint32_t sb = smem_u32(sm);
    const int tid = threadIdx.x, wp = tid >> 5, lane = tid & 31;
    const int g = lane >> 2, t = lane & 3;
    const int mw = wp >> 1, nw = wp & 1;
    const int n0 = blockIdx.x * 64, m0 = blockIdx.y * 128;

    float* bos = (float*)(sm + OP_BO);
    if (tid < 64) bos[tid] = bo[n0 + tid];

    op_issue(sb, m0, n0, 0, tid);
    CP_COMMIT();

    float acc[2][4][4];
#pragma unroll
    for (int mi = 0; mi < 2; mi++)
#pragma unroll
        for (int ni = 0; ni < 4; ni++)
#pragma unroll
            for (int j = 0; j < 4; j++) acc[mi][ni][j] = 0.f;

    const uint32_t aOff = (uint32_t)(mw*32 + (lane & 7) + ((lane >> 3) & 1) * 8) * 144
                        + (lane >> 4) * 16;
    const uint32_t bOff = (uint32_t)(nw*32 + (lane & 7)) * 144
                        + ((lane >> 3) & 1) * 16;

    for (int kt = 0; kt < 16; kt++) {
        const uint32_t stg = sb + (uint32_t)(kt & 1) * OP_STAGE;
        if (kt < 15) {
            op_issue(sb + (uint32_t)((kt + 1) & 1) * OP_STAGE, m0, n0, kt + 1, tid);
            CP_COMMIT();
            CP_WAIT1();
        } else {
            CP_WAIT0();
        }
        __syncthreads();

#pragma unroll
        for (int kc = 0; kc < 4; kc++) {
            uint32_t bfh[4][2], bfl[4][2];
#pragma unroll
            for (int ni = 0; ni < 4; ni++) {
                ldsm2(bfh[ni], stg + OB_H + bOff + ni*1152 + kc*32);
                ldsm2(bfl[ni], stg + OB_L + bOff + ni*1152 + kc*32);
            }
#pragma unroll
            for (int mi = 0; mi < 2; mi++) {
                uint32_t ah[4], al[4];
                ldsm4(ah, stg + OA_H + aOff + mi*2304 + kc*32);
                ldsm4(al, stg + OA_L + aOff + mi*2304 + kc*32);
#pragma unroll
                for (int ni = 0; ni < 4; ni++) {
                    mma16816(acc[mi][ni], ah, bfh[ni]);
                    mma16816(acc[mi][ni], al, bfh[ni]);
                    mma16816(acc[mi][ni], ah, bfl[ni]);
                }
            }
        }
        __syncthreads();
    }

    // epilogue: + bias, float2 stores
#pragma unroll
    for (int mi = 0; mi < 2; mi++) {
        const int row0 = m0 + mw*32 + mi*16 + g;
#pragma unroll
        for (int ni = 0; ni < 4; ni++) {
            const int col = nw*32 + ni*8 + 2*t;
            float2 b2 = *(const float2*)(bos + col);
            float2 o0 = {acc[mi][ni][0] + b2.x, acc[mi][ni][1] + b2.y};
            float2 o1 = {acc[mi][ni][2] + b2.x, acc[mi][ni][3] + b2.y};
            *(float2*)(out + (size_t)row0 * DMODEL + n0 + col) = o0;
            *(float2*)(out + (size_t)(row0 + 8) * DMODEL + n0 + col) = o1;
        }
    }
}

// ---------------------------------------------------------------------------
extern "C" void kernel_launch(void* const* d_in, const int* in_sizes, int n_in,
                              void* d_out, int out_size)
{
    const float* q    = (const float*)d_in[0];
    const float* k    = (const float*)d_in[1];
    const float* v    = (const float*)d_in[2];
    const float* pt   = (const float*)d_in[3];
    const float* bias = (const float*)d_in[4];
    const float* W1   = (const float*)d_in[5];
    const float* b1   = (const float*)d_in[6];
    const float* w2   = (const float*)d_in[7];
    const float* b2   = (const float*)d_in[8];
    const float* Wo   = (const float*)d_in[9];
    const float* bo   = (const float*)d_in[10];

    float* graph_out = (float*)d_out;                              // [8,1024,1024]
    float* weights   = (float*)d_out + (size_t)Bb * Ll * DMODEL;   // [8,16,1024,1024]

    cudaFuncSetAttribute(attn_mma,
        cudaFuncAttributeMaxDynamicSharedMemorySize, ATTN3_SMEM);
    cudaFuncSetAttribute(outproj_mma,
        cudaFuncAttributeMaxDynamicSharedMemorySize, OUT3_SMEM);

    gate_kernel<<<BH * Ll / 8, 256>>>(pt, W1, b1, w2, b2);
    prep_wo_kernel<<<DMODEL * DMODEL / 256, 256>>>(Wo);
    attn_mma<<<dim3(Ll / 128, BH), 256, ATTN3_SMEM>>>(q, k, v, bias, weights);
    outproj_mma<<<dim3(DMODEL / 64, Bb * Ll / 128), 256, OUT3_SMEM>>>(bo, graph_out);
}

// round 16
// speedup vs baseline: 2.3498x; 1.0240x over previous
#include <cuda_runtime.h>
#include <cuda_bf16.h>
#include <cstdint>
#include <cstddef>

#define Bb 8
#define Hh 16
#define Ll 1024
#define Dd 64
#define BH (Bb*Hh)
#define DMODEL (Hh*Dd)

// scratch (no allocations allowed)
__device__ float g_gate[BH*Ll];
__device__ __nv_bfloat16 g_qh[(size_t)BH*Ll*Dd];       // pre-split Q*scale hi
__device__ __nv_bfloat16 g_ql[(size_t)BH*Ll*Dd];       // lo
__device__ __nv_bfloat16 g_kh[(size_t)BH*Ll*Dd];
__device__ __nv_bfloat16 g_kl[(size_t)BH*Ll*Dd];
__device__ __nv_bfloat16 g_vh[(size_t)BH*Ll*Dd];
__device__ __nv_bfloat16 g_vl[(size_t)BH*Ll*Dd];
__device__ __nv_bfloat16 g_aoh[(size_t)Bb*Ll*DMODEL];  // attnout hi [b*L+l][h*64+d]
__device__ __nv_bfloat16 g_aol[(size_t)Bb*Ll*DMODEL];  // attnout lo
__device__ __nv_bfloat16 g_woh[DMODEL*DMODEL];         // W_out hi [n][k]
__device__ __nv_bfloat16 g_wol[DMODEL*DMODEL];         // W_out lo

// ---- split helper: (a,b) -> packed bf16x2 hi and lo ----
__device__ __forceinline__ void split2(float a, float b, uint32_t& h, uint32_t& l) {
    __nv_bfloat16 ha = __float2bfloat16(a), hb = __float2bfloat16(b);
    __nv_bfloat16 la = __float2bfloat16(a - __bfloat162float(ha));
    __nv_bfloat16 lb = __float2bfloat16(b - __bfloat162float(hb));
    h = (uint32_t)__bfloat16_as_ushort(ha) | ((uint32_t)__bfloat16_as_ushort(hb) << 16);
    l = (uint32_t)__bfloat16_as_ushort(la) | ((uint32_t)__bfloat16_as_ushort(lb) << 16);
}

// ---- raw tensor-core / async primitives (baseline PTX, ok for compute_103) ----
__device__ __forceinline__ void ldsm4(uint32_t* r, uint32_t a) {
    asm volatile("ldmatrix.sync.aligned.m8n8.x4.shared.b16 {%0,%1,%2,%3}, [%4];"
        : "=r"(r[0]), "=r"(r[1]), "=r"(r[2]), "=r"(r[3]) : "r"(a));
}
__device__ __forceinline__ void ldsm2(uint32_t* r, uint32_t a) {
    asm volatile("ldmatrix.sync.aligned.m8n8.x2.shared.b16 {%0,%1}, [%2];"
        : "=r"(r[0]), "=r"(r[1]) : "r"(a));
}
__device__ __forceinline__ void ldsm2t(uint32_t* r, uint32_t a) {
    asm volatile("ldmatrix.sync.aligned.m8n8.x2.trans.shared.b16 {%0,%1}, [%2];"
        : "=r"(r[0]), "=r"(r[1]) : "r"(a));
}
__device__ __forceinline__ void mma16816(float* c, const uint32_t* a, const uint32_t* b) {
    asm volatile("mma.sync.aligned.m16n8k16.row.col.f32.bf16.bf16.f32 "
        "{%0,%1,%2,%3}, {%4,%5,%6,%7}, {%8,%9}, {%0,%1,%2,%3};"
        : "+f"(c[0]), "+f"(c[1]), "+f"(c[2]), "+f"(c[3])
        : "r"(a[0]), "r"(a[1]), "r"(a[2]), "r"(a[3]), "r"(b[0]), "r"(b[1]));
}
__device__ __forceinline__ uint32_t smem_u32(const void* p) {
    uint32_t a;
    asm("{ .reg .u64 t; cvta.to.shared.u64 t, %1; cvt.u32.u64 %0, t; }"
        : "=r"(a) : "l"(p));
    return a;
}
__device__ __forceinline__ void cp16(uint32_t dst, const void* src) {
    asm volatile("cp.async.cg.shared.global [%0], [%1], 16;"
        :: "r"(dst), "l"(src) : "memory");
}
#define CP_COMMIT() asm volatile("cp.async.commit_group;" ::: "memory")
#define CP_WAIT0()  asm volatile("cp.async.wait_group 0;" ::: "memory")
#define CP_WAIT1()  asm volatile("cp.async.wait_group 1;" ::: "memory")
#define CP_WAIT2()  asm volatile("cp.async.wait_group 2;" ::: "memory")

// ---------------- K1: gate ----------------
__global__ __launch_bounds__(256) void gate_kernel(
    const float* __restrict__ pt, const float* __restrict__ W1,
    const float* __restrict__ b1, const float* __restrict__ w2,
    const float* __restrict__ b2)
{
    __shared__ float W1s[64][65];
    __shared__ float w2s[64], b1s[64], pts[8][64];
    const int tid = threadIdx.x;
    for (int i = tid; i < 64*64; i += 256) W1s[i >> 6][i & 63] = W1[i];
    if (tid < 64) { w2s[tid] = w2[tid]; b1s[tid] = b1[tid]; }
    __syncthreads();
    const int warp = tid >> 5, lane = tid & 31;
    const size_t row = (size_t)blockIdx.x * 8 + warp;
    const float* p = pt + row * Dd;
    pts[warp][lane] = p[lane];
    pts[warp][lane + 32] = p[lane + 32];
    __syncwarp();
    float a0 = 0.f, a1 = 0.f;
#pragma unroll
    for (int d = 0; d < 64; d++) {
        float x = pts[warp][d];
        a0 = fmaf(x, W1s[lane][d], a0);
        a1 = fmaf(x, W1s[lane + 32][d], a1);
    }
    float part = tanhf(a0 + b1s[lane]) * w2s[lane]
               + tanhf(a1 + b1s[lane + 32]) * w2s[lane + 32];
#pragma unroll
    for (int off = 16; off > 0; off >>= 1)
        part += __shfl_xor_sync(0xffffffffu, part, off);
    if (lane == 0)
        g_gate[row] = 1.0f / (1.0f + __expf(-(part + b2[0])));
}

// ---------------- prep: W_out -> bf16 hi/lo ----------------
__global__ __launch_bounds__(256) void prep_wo_kernel(const float* __restrict__ W)
{
    int i = blockIdx.x * 256 + threadIdx.x;
    float x = W[i];
    __nv_bfloat16 h = __float2bfloat16(x);
    g_woh[i] = h;
    g_wol[i] = __float2bfloat16(x - __bfloat162float(h));
}

// ---------------- prep: Q/K/V -> bf16 hi/lo (Q pre-scaled) -----------------
__global__ __launch_bounds__(256) void prep_qkv_kernel(
    const float* __restrict__ q, const float* __restrict__ k,
    const float* __restrict__ v)
{
    const int which = blockIdx.y;
    const float* src = (which == 0) ? q : (which == 1) ? k : v;
    __nv_bfloat16* dh = (which == 0) ? g_qh : (which == 1) ? g_kh : g_vh;
    __nv_bfloat16* dl = (which == 0) ? g_ql : (which == 1) ? g_kl : g_vl;
    const float scale = (which == 0) ? 0.125f : 1.0f;
    size_t i = ((size_t)blockIdx.x * 256 + threadIdx.x) * 4;
    float4 x4 = *(const float4*)(src + i);
    uint32_t h0, l0, h1, l1;
    split2(x4.x * scale, x4.y * scale, h0, l0);
    split2(x4.z * scale, x4.w * scale, h1, l1);
    *(uint2*)(dh + i) = make_uint2(h0, h1);
    *(uint2*)(dl + i) = make_uint2(l0, l1);
}

// ---------------- attn: pre-split operands, double-buffered KV cp.async ----
// smem: buf0 [0,36864): KH 9216 | KL 9216 | VH 9216 | VL 9216  (Q hi/lo at init)
//       buf1 [36864,73728): same layout
//       bias [73728,108544): 128 rows x 272 B  (reused as inv[128] at tail)
//       gate [108544,108800): 64 f32
#define S_BUF1 36864u
#define S_BIAS 73728u
#define S_GT   108544u
#define ATTN4_SMEM 108800

__device__ __forceinline__ void attn_issue_kv(uint32_t bufb, size_t kvb,
                                              int kt, int tid) {
    const __nv_bfloat16* s0 = g_kh + kvb + (size_t)kt * 64 * Dd;
    const __nv_bfloat16* s1 = g_kl + kvb + (size_t)kt * 64 * Dd;
    const __nv_bfloat16* s2 = g_vh + kvb + (size_t)kt * 64 * Dd;
    const __nv_bfloat16* s3 = g_vl + kvb + (size_t)kt * 64 * Dd;
#pragma unroll
    for (int j = 0; j < 8; j++) {
        const int ci = tid + (j & 1) * 256;        // 0..511 (64 rows x 8 chunks)
        const int row = ci >> 3, c = ci & 7;
        const __nv_bfloat16* sp = (j < 2) ? s0 : (j < 4) ? s1 : (j < 6) ? s2 : s3;
        const uint32_t arr = (uint32_t)(j >> 1);
        cp16(bufb + arr * 9216u + row * 144 + c * 16,
             sp + (size_t)row * 64 + c * 8);
    }
}

__global__ __launch_bounds__(256, 2) void attn_mma(
    const float* __restrict__ bias, float* __restrict__ wout)
{
    extern __shared__ char sm[];
    const uint32_t sb = smem_u32(sm);
    const float* gt = (const float*)(sm + S_GT);
    const float* bsm = (const float*)(sm + S_BIAS);

    const int tid = threadIdx.x, wp = tid >> 5, lane = tid & 31;
    const int g = lane >> 2, t = lane & 3;
    const int bh = blockIdx.y, b = bh >> 4, h = bh & 15;
    const int q0 = blockIdx.x * 128;
    const size_t kvb = (size_t)bh * Ll * Dd;
    const int r0 = wp * 16;

    // Q preamble: cp.async pre-split Q hi/lo into buf0, ldsm to regs
    {
        const __nv_bfloat16* qh = g_qh + kvb + (size_t)q0 * Dd;
        const __nv_bfloat16* ql = g_ql + kvb + (size_t)q0 * Dd;
#pragma unroll
        for (int j = 0; j < 8; j++) {
            const int ci = tid + (j & 3) * 256;     // 0..1023 (128 rows x 8)
            const int row = ci >> 3, c = ci & 7;
            const __nv_bfloat16* sp = (j < 4) ? qh : ql;
            const uint32_t base = (j < 4) ? 0u : 18432u;
            cp16(sb + base + row * 144 + c * 16, sp + (size_t)row * 64 + c * 8);
        }
        CP_COMMIT();
        CP_WAIT0();
    }
    __syncthreads();
    uint32_t qfh[4][4], qfl[4][4];
    {
        const int a_row = r0 + (lane & 7) + ((lane >> 3) & 1) * 8;
        const int a_col = (lane >> 4) * 8;
        const uint32_t qhA = sb + a_row*144 + a_col*2;
#pragma unroll
        for (int kc = 0; kc < 4; kc++) {
            ldsm4(qfh[kc], qhA + kc*32);
            ldsm4(qfl[kc], qhA + 18432u + kc*32);
        }
    }
    __syncthreads();   // Q in regs; buffers free

    // ldsm lane bases (per-buffer offsets)
    const uint32_t off_kB = (uint32_t)((lane & 7)*144 + (((lane >> 3) & 1) * 8)*2);
    const uint32_t off_v  = (uint32_t)(((lane & 7) + ((lane >> 3) & 1) * 8)*144);

    float oacc[8][4];
#pragma unroll
    for (int c = 0; c < 8; c++)
#pragma unroll
        for (int j = 0; j < 4; j++) oacc[c][j] = 0.f;
    float rs0 = 0.f, rs1 = 0.f;

    const size_t rowg  = (size_t)bh * Ll * Ll + (size_t)(q0 + r0 + g) * Ll;
    const size_t rowg8 = rowg + 8 * (size_t)Ll;
    const uint32_t brow0 = (uint32_t)(r0 + g) * 68;
    const uint32_t brow8 = brow0 + 8 * 68;
    const float* bias_base = bias + (size_t)bh * Ll * Ll + (size_t)q0 * Ll;
    const float* gate_base = g_gate + (size_t)bh * Ll;

    // preloop: groups = KV(0), bias+gate(0), KV(1)
    attn_issue_kv(sb, kvb, 0, tid);
    CP_COMMIT();
    {
#pragma unroll
        for (int j = 0; j < 8; j++) {
            int ci = tid + j * 256;
            int row = ci >> 4, c16 = ci & 15;
            cp16(sb + S_BIAS + row*272 + c16*16,
                 bias_base + (size_t)row * Ll + c16 * 4);
        }
        if (tid < 16) cp16(sb + S_GT + tid*16, gate_base + tid*4);
        CP_COMMIT();
    }
    attn_issue_kv(sb + S_BUF1, kvb, 1, tid);
    CP_COMMIT();

    for (int kt = 0; kt < 16; kt++) {
        const uint32_t buf = sb + (uint32_t)(kt & 1) * S_BUF1;
        // groups in flight at top: KV(kt), bias(kt), KV(kt+1) when kt<15
        if (kt < 15) CP_WAIT2(); else CP_WAIT1();   // KV(kt) resident
        __syncthreads();

        // QK^T: 3-term, Q from regs, K from buf
        const uint32_t khB = buf + off_kB;
        const uint32_t klB = buf + 9216u + off_kB;
        float sacc[8][4];
#pragma unroll
        for (int c = 0; c < 8; c++)
#pragma unroll
            for (int j = 0; j < 4; j++) sacc[c][j] = 0.f;
#pragma unroll
        for (int kc = 0; kc < 4; kc++) {
#pragma unroll
            for (int c = 0; c < 8; c++) {
                uint32_t bh2[2], bl2[2];
                ldsm2(bh2, khB + c*1152 + kc*32);
                ldsm2(bl2, klB + c*1152 + kc*32);
                mma16816(sacc[c], qfh[kc], bh2);
                mma16816(sacc[c], qfl[kc], bh2);
                mma16816(sacc[c], qfh[kc], bl2);
            }
        }

        if (kt < 15) CP_WAIT1(); else CP_WAIT0();   // bias+gate(kt) resident
        __syncthreads();

        // in-register epilogue: +bias, exp, rsum, *gate, STG weights
        {
            float* wg  = wout + rowg  + kt*64 + 2*t;
            float* wg8 = wout + rowg8 + kt*64 + 2*t;
#pragma unroll
            for (int c = 0; c < 8; c++) {
                float2 bv0 = *(const float2*)(bsm + brow0 + 2*t + 8*c);
                float2 bv1 = *(const float2*)(bsm + brow8 + 2*t + 8*c);
                float e00 = __expf(sacc[c][0] + bv0.x);
                float e01 = __expf(sacc[c][1] + bv0.y);
                float e10 = __expf(sacc[c][2] + bv1.x);
                float e11 = __expf(sacc[c][3] + bv1.y);
                rs0 += e00 + e01;
                rs1 += e10 + e11;
                float2 gv = *(const float2*)(gt + c*8 + 2*t);
                float w00 = e00 * gv.x, w01 = e01 * gv.y;
                float w10 = e10 * gv.x, w11 = e11 * gv.y;
                float2 o0 = {w00, w01}, o1 = {w10, w11};
                *(float2*)(wg  + c*8) = o0;
                *(float2*)(wg8 + c*8) = o1;
                sacc[c][0] = w00; sacc[c][1] = w01;
                sacc[c][2] = w10; sacc[c][3] = w11;
            }
        }

        // P*V: 3-term, P fragments built in-register, V from buf
        const uint32_t vhB = buf + 18432u + off_v;
        const uint32_t vlB = buf + 27648u + off_v;
#pragma unroll
        for (int kc = 0; kc < 4; kc++) {
            uint32_t ph[4], pl[4];
            split2(sacc[2*kc][0],   sacc[2*kc][1],   ph[0], pl[0]);
            split2(sacc[2*kc][2],   sacc[2*kc][3],   ph[1], pl[1]);
            split2(sacc[2*kc+1][0], sacc[2*kc+1][1], ph[2], pl[2]);
            split2(sacc[2*kc+1][2], sacc[2*kc+1][3], ph[3], pl[3]);
#pragma unroll
            for (int cd = 0; cd < 8; cd++) {
                uint32_t vh2[2], vl2[2];
                ldsm2t(vh2, vhB + kc*2304 + cd*16);
                ldsm2t(vl2, vlB + kc*2304 + cd*16);
                mma16816(oacc[cd], ph, vh2);
                mma16816(oacc[cd], pl, vh2);
                mma16816(oacc[cd], ph, vl2);
            }
        }
        __syncthreads();     // bias/gate reads + KV(kt) reads done

        // prefetch bias+gate(kt+1), then KV(kt+2) into the freed buffer
        if (kt < 15) {
#pragma unroll
            for (int j = 0; j < 8; j++) {
                int ci = tid + j * 256;
                int row = ci >> 4, c16 = ci & 15;
                cp16(sb + S_BIAS + row*272 + c16*16,
                     bias_base + (size_t)row * Ll + (kt + 1) * 64 + c16 * 4);
            }
            if (tid < 16)
                cp16(sb + S_GT + tid*16, gate_base + (kt + 1) * 64 + tid*4);
            CP_COMMIT();
        }
        if (kt < 14) {
            attn_issue_kv(sb + (uint32_t)(kt & 1) * S_BUF1, kvb, kt + 2, tid);
            CP_COMMIT();
        }
    }

    // rowsum reduce (within quad), normalized O -> g_ao hi/lo
    rs0 += __shfl_xor_sync(0xffffffffu, rs0, 1);
    rs0 += __shfl_xor_sync(0xffffffffu, rs0, 2);
    rs1 += __shfl_xor_sync(0xffffffffu, rs1, 1);
    rs1 += __shfl_xor_sync(0xffffffffu, rs1, 2);
    const float inv0 = 1.0f / rs0, inv1 = 1.0f / rs1;
    {
        const size_t m0r = (size_t)b * 1024 + q0 + r0 + g;
        uint32_t* dh0 = (uint32_t*)g_aoh + m0r * (DMODEL/2) + h * 32;
        uint32_t* dl0 = (uint32_t*)g_aol + m0r * (DMODEL/2) + h * 32;
        uint32_t* dh8 = dh0 + 8 * (DMODEL/2);
        uint32_t* dl8 = dl0 + 8 * (DMODEL/2);
#pragma unroll
        for (int cd = 0; cd < 8; cd++) {
            uint32_t hh, ll;
            split2(oacc[cd][0] * inv0, oacc[cd][1] * inv0, hh, ll);
            dh0[cd*4 + t] = hh; dl0[cd*4 + t] = ll;
            split2(oacc[cd][2] * inv1, oacc[cd][3] * inv1, hh, ll);
            dh8[cd*4 + t] = hh; dl8[cd*4 + t] = ll;
        }
    }

    // fused normalize of this CTA's 128 weight rows
    {
        float* invs = (float*)(sm + S_BIAS);
        __syncthreads();
        if (t == 0) {
            invs[r0 + g]     = inv0;
            invs[r0 + g + 8] = inv1;
        }
        __syncthreads();
        float* wbase = wout + (size_t)bh * Ll * Ll + (size_t)q0 * Ll;
#pragma unroll 4
        for (int j = 0; j < 128; j++) {
            float inv = invs[j];
            float4* p = (float4*)(wbase + (size_t)j * Ll) + tid;
            float4 x = *p;
            x.x *= inv; x.y *= inv; x.z *= inv; x.w *= inv;
            *p = x;
        }
    }
}

// ---------------- outproj: 128x64 tiles, 2-stage cp.async, 2 CTAs/SM --------
#define OA_H 0u
#define OA_L 18432u
#define OB_H 36864u
#define OB_L 46080u
#define OP_STAGE 55296u
#define OP_BO (2u*OP_STAGE)
#define OUT3_SMEM 110848

__device__ __forceinline__ void op_issue(uint32_t st, int m0, int n0,
                                         int kt, int tid) {
#pragma unroll
    for (int j = 0; j < 4; j++) {
        int ci = tid + j * 256;
        int row = ci >> 3, c16 = ci & 7;
        uint32_t doff = (uint32_t)row * 144 + c16 * 16;
        size_t aoff = ((size_t)(m0 + row) * 512 + kt * 32 + c16 * 4) * 4;
        cp16(st + OA_H + doff, (const char*)g_aoh + aoff);
        cp16(st + OA_L + doff, (const char*)g_aol + aoff);
    }
#pragma unroll
    for (int j = 0; j < 2; j++) {
        int ci = tid + j * 256;
        int row = ci >> 3, c16 = ci & 7;
        uint32_t doff = (uint32_t)row * 144 + c16 * 16;
        size_t boff = ((size_t)(n0 + row) * 512 + kt * 32 + c16 * 4) * 4;
        cp16(st + OB_H + doff, (const char*)g_woh + boff);
        cp16(st + OB_L + doff, (const char*)g_wol + boff);
    }
}

__global__ __launch_bounds__(256, 2) void outproj_mma(
    const float* __restrict__ bo, float* __restrict__ out)
{
    extern __shared__ char sm[];
    const uint32_t sb = smem_u32(sm);
    const int tid = threadIdx.x, wp = tid >> 5, lane = tid & 31;
    const int g = lane >> 2, t = lane & 3;
    const int mw = wp >> 1, nw = wp & 1;
    const int n0 = blockIdx.x * 64, m0 = blockIdx.y * 128;

    float* bos = (float*)(sm + OP_BO);
    if (tid < 64) bos[tid] = bo[n0 + tid];

    op_issue(sb, m0, n0, 0, tid);
    CP_COMMIT();

    float acc[2][4][4];
#pragma unroll
    for (int mi = 0; mi < 2; mi++)
#pragma unroll
        for (int ni = 0; ni < 4; ni++)
#pragma unroll
            for (int j = 0; j < 4; j++) acc[mi][ni][j] = 0.f;

    const uint32_t aOff = (uint32_t)(mw*32 + (lane & 7) + ((lane >> 3) & 1) * 8) * 144
                        + (lane >> 4) * 16;
    const uint32_t bOff = (uint32_t)(nw*32 + (lane & 7)) * 144
                        + ((lane >> 3) & 1) * 16;

    for (int kt = 0; kt < 16; kt++) {
        const uint32_t stg = sb + (uint32_t)(kt & 1) * OP_STAGE;
        if (kt < 15) {
            op_issue(sb + (uint32_t)((kt + 1) & 1) * OP_STAGE, m0, n0, kt + 1, tid);
            CP_COMMIT();
            CP_WAIT1();
        } else {
            CP_WAIT0();
        }
        __syncthreads();

#pragma unroll
        for (int kc = 0; kc < 4; kc++) {
            uint32_t bfh[4][2], bfl[4][2];
#pragma unroll
            for (int ni = 0; ni < 4; ni++) {
                ldsm2(bfh[ni], stg + OB_H + bOff + ni*1152 + kc*32);
                ldsm2(bfl[ni], stg + OB_L + bOff + ni*1152 + kc*32);
            }
#pragma unroll
            for (int mi = 0; mi < 2; mi++) {
                uint32_t ah[4], al[4];
                ldsm4(ah, stg + OA_H + aOff + mi*2304 + kc*32);
                ldsm4(al, stg + OA_L + aOff + mi*2304 + kc*32);
#pragma unroll
                for (int ni = 0; ni < 4; ni++) {
                    mma16816(acc[mi][ni], ah, bfh[ni]);
                    mma16816(acc[mi][ni], al, bfh[ni]);
                    mma16816(acc[mi][ni], ah, bfl[ni]);
                }
            }
        }
        __syncthreads();
    }

#pragma unroll
    for (int mi = 0; mi < 2; mi++) {
        const int row0 = m0 + mw*32 + mi*16 + g;
#pragma unroll
        for (int ni = 0; ni < 4; ni++) {
            const int col = nw*32 + ni*8 + 2*t;
            float2 b2 = *(const float2*)(bos + col);
            float2 o0 = {acc[mi][ni][0] + b2.x, acc[mi][ni][1] + b2.y};
            float2 o1 = {acc[mi][ni][2] + b2.x, acc[mi][ni][3] + b2.y};
            *(float2*)(out + (size_t)row0 * DMODEL + n0 + col) = o0;
            *(float2*)(out + (size_t)(row0 + 8) * DMODEL + n0 + col) = o1;
        }
    }
}

// ---------------------------------------------------------------------------
extern "C" void kernel_launch(void* const* d_in, const int* in_sizes, int n_in,
                              void* d_out, int out_size)
{
    const float* q    = (const float*)d_in[0];
    const float* k    = (const float*)d_in[1];
    const float* v    = (const float*)d_in[2];
    const float* pt   = (const float*)d_in[3];
    const float* bias = (const float*)d_in[4];
    const float* W1   = (const float*)d_in[5];
    const float* b1   = (const float*)d_in[6];
    const float* w2   = (const float*)d_in[7];
    const float* b2   = (const float*)d_in[8];
    const float* Wo   = (const float*)d_in[9];
    const float* bo   = (const float*)d_in[10];

    float* graph_out = (float*)d_out;                              // [8,1024,1024]
    float* weights   = (float*)d_out + (size_t)Bb * Ll * DMODEL;   // [8,16,1024,1024]

    cudaFuncSetAttribute(attn_mma,
        cudaFuncAttributeMaxDynamicSharedMemorySize, ATTN4_SMEM);
    cudaFuncSetAttribute(outproj_mma,
        cudaFuncAttributeMaxDynamicSharedMemorySize, OUT3_SMEM);

    gate_kernel<<<BH * Ll / 8, 256>>>(pt, W1, b1, w2, b2);
    prep_wo_kernel<<<DMODEL * DMODEL / 256, 256>>>(Wo);
    prep_qkv_kernel<<<dim3((BH * Ll * Dd) / 1024, 3), 256>>>(q, k, v);
    attn_mma<<<dim3(Ll / 128, BH), 256, ATTN4_SMEM>>>(bias, weights);
    outproj_mma<<<dim3(DMODEL / 64, Bb * Ll / 128), 256, OUT3_SMEM>>>(bo, graph_out);
}